// round 14
// baseline (speedup 1.0000x reference)
#include <cuda_runtime.h>
#include <cuda_bf16.h>
#include <math.h>
#include <stdint.h>

#define cB 32
#define cS 64
#define cT 64
#define cE 512
#define cH 1024
#define cG 4096
#define cV 32000
#define cKC 3072

// ---- scratch layout (float offsets) ----
#define OFF_GF      0ull
#define OFF_GB      8388608ull
#define OFF_GD      16777216ull
#define OFF_GATES   25165824ull   // 8 slots x 32768 (decbias parts)
#define OFF_HF      25690112ull
#define OFF_CF      25722880ull
#define OFF_HB      25755648ull
#define OFF_CB      25788416ull
#define OFF_SUMF    25821184ull
#define OFF_SUMB    25853952ull
#define OFF_HD      25886720ull
#define OFF_CD      25919488ull
#define OFF_DECB    25952256ull
#define OFF_HDEC    25985024ull
#define OFF_OUTS    28082176ull
#define SCR_TOTAL   30179328ull

__device__ float g_scr[SCR_TOTAL];
__device__ __nv_bfloat16 g_Acat[(size_t)2048 * cKC];
__device__ __nv_bfloat16 g_Wcat[(size_t)cV * cKC];
__device__ __nv_bfloat16 g_WihC[3][(size_t)cG * 1536];
__device__ __nv_bfloat16 g_WhhC[3][(size_t)cG * 3072];   // gate-interleaved rows 4j+g
__device__ __nv_bfloat16 g_AE[(size_t)2048 * 1536];
__device__ __nv_bfloat16 g_AD[(size_t)2048 * 1536];
__device__ __nv_bfloat16 g_hc[6 * 32 * 3072];            // F0,F1,B0,B1,D0,D1

typedef unsigned long long u64;

__device__ __forceinline__ float sigf(float x) { return 1.0f / (1.0f + expf(-x)); }
__device__ __forceinline__ u64 splat2(float a) {
    u64 r; asm("mov.b64 %0, {%1, %1};" : "=l"(r) : "f"(a)); return r;
}
__device__ __forceinline__ void fma2(u64& d, u64 a, u64 b) {
    asm("fma.rn.f32x2 %0, %1, %2, %0;" : "+l"(d) : "l"(a), "l"(b));
}
__device__ __forceinline__ float2 unpk(u64 v) {
    float2 f; asm("mov.b64 {%0, %1}, %2;" : "=f"(f.x), "=f"(f.y) : "l"(v)); return f;
}
__device__ __forceinline__ unsigned smem_u32(const void* p) {
    unsigned r;
    asm("{ .reg .u64 t; cvta.to.shared.u64 t, %1; cvt.u32.u64 %0, t; }" : "=r"(r) : "l"(p));
    return r;
}
__device__ __forceinline__ void bf16split(float x, __nv_bfloat16& h, __nv_bfloat16& l) {
    h = __float2bfloat16(x);
    l = __float2bfloat16(x - __bfloat162float(h));
}

// ============ split K=1024 -> 3072 [hi|hi|lo]   (Wout)
__global__ void k_splitW(const float* __restrict__ W, __nv_bfloat16* __restrict__ C, int rows)
{
    int i = blockIdx.x * 256 + threadIdx.x;
    if (i >= rows * 512) return;
    int n = i >> 9, k2 = i & 511;
    float2 w = *(const float2*)&W[(size_t)n * cH + k2 * 2];
    __nv_bfloat16 h0, l0, h1, l1;
    bf16split(w.x, h0, l0); bf16split(w.y, h1, l1);
    __nv_bfloat162 hh; hh.x = h0; hh.y = h1;
    __nv_bfloat162 ll; ll.x = l0; ll.y = l1;
    __nv_bfloat162* R = (__nv_bfloat162*)(C + (size_t)n * 3072);
    R[k2] = hh; R[512 + k2] = hh; R[1024 + k2] = ll;
}

// ============ split+PERMUTE Whh: out row = 4*j + g for input row g*1024+j, [hi|hi|lo]
__global__ void k_splitWhhP(const float* __restrict__ W, __nv_bfloat16* __restrict__ C)
{
    int i = blockIdx.x * 256 + threadIdx.x;
    if (i >= cG * 512) return;
    int n = i >> 9, k2 = i & 511;
    int g = n >> 10, j = n & 1023;
    int outRow = (j << 2) | g;
    float2 w = *(const float2*)&W[(size_t)n * cH + k2 * 2];
    __nv_bfloat16 h0, l0, h1, l1;
    bf16split(w.x, h0, l0); bf16split(w.y, h1, l1);
    __nv_bfloat162 hh; hh.x = h0; hh.y = h1;
    __nv_bfloat162 ll; ll.x = l0; ll.y = l1;
    __nv_bfloat162* R = (__nv_bfloat162*)(C + (size_t)outRow * 3072);
    R[k2] = hh; R[512 + k2] = hh; R[1024 + k2] = ll;
}

// ============ split K=1024 -> 3072 [hi|lo|hi]   (logits A)
__global__ void k_splitA(const float* __restrict__ A, __nv_bfloat16* __restrict__ C, int rows)
{
    int i = blockIdx.x * 256 + threadIdx.x;
    if (i >= rows * 512) return;
    int m = i >> 9, k2 = i & 511;
    float2 w = *(const float2*)&A[(size_t)m * cH + k2 * 2];
    __nv_bfloat16 h0, l0, h1, l1;
    bf16split(w.x, h0, l0); bf16split(w.y, h1, l1);
    __nv_bfloat162 hh; hh.x = h0; hh.y = h1;
    __nv_bfloat162 ll; ll.x = l0; ll.y = l1;
    __nv_bfloat162* R = (__nv_bfloat162*)(C + (size_t)m * 3072);
    R[k2] = hh; R[512 + k2] = ll; R[1024 + k2] = hh;
}

// ============ split K=512 -> 1536 [hi|hi|lo]   (Wih_*)
__global__ void k_splitW512(const float* __restrict__ W, __nv_bfloat16* __restrict__ C, int rows)
{
    int i = blockIdx.x * 256 + threadIdx.x;
    if (i >= rows * 256) return;
    int n = i >> 8, k2 = i & 255;
    float2 w = *(const float2*)&W[(size_t)n * cE + k2 * 2];
    __nv_bfloat16 h0, l0, h1, l1;
    bf16split(w.x, h0, l0); bf16split(w.y, h1, l1);
    __nv_bfloat162 hh; hh.x = h0; hh.y = h1;
    __nv_bfloat162 ll; ll.x = l0; ll.y = l1;
    __nv_bfloat162* R = (__nv_bfloat162*)(C + (size_t)n * 1536);
    R[k2] = hh; R[256 + k2] = hh; R[512 + k2] = ll;
}

// ============ token gather + split K=512 -> 1536 [hi|lo|hi]
__global__ void k_gather512(const int* __restrict__ tok, const float* __restrict__ emb,
                            __nv_bfloat16* __restrict__ C)
{
    int i = blockIdx.x * 256 + threadIdx.x;
    int m = i >> 8, k2 = i & 255;
    int trow = tok[(m & 31) * 64 + (m >> 5)];
    float2 w = *(const float2*)&emb[(size_t)trow * cE + k2 * 2];
    __nv_bfloat16 h0, l0, h1, l1;
    bf16split(w.x, h0, l0); bf16split(w.y, h1, l1);
    __nv_bfloat162 hh; hh.x = h0; hh.y = h1;
    __nv_bfloat162 ll; ll.x = l0; ll.y = l1;
    __nv_bfloat162* R = (__nv_bfloat162*)(C + (size_t)m * 1536);
    R[k2] = hh; R[256 + k2] = ll; R[512 + k2] = hh;
}

#define STRD 80

// ============ HMMA logits GEMM (validated)
__global__ __launch_bounds__(256, 2)
void k_logits_mma(const __nv_bfloat16* __restrict__ Acat,
                  const __nv_bfloat16* __restrict__ Wcat,
                  const float* __restrict__ bout, float* __restrict__ out)
{
    __shared__ char sm[2][2 * 128 * STRD];
    const int tid = threadIdx.x, wid = tid >> 5, lane = tid & 31;
    const int m0 = blockIdx.x * 128, n0 = blockIdx.y * 128;
    const int warp_m = (wid & 1) * 64, warp_n = (wid >> 1) * 32;

    float acc[4][4][4];
    #pragma unroll
    for (int a = 0; a < 4; a++)
        #pragma unroll
        for (int b = 0; b < 4; b++)
            #pragma unroll
            for (int d = 0; d < 4; d++) acc[a][b][d] = 0.f;

    const int g0 = tid, g1 = tid + 256;
    const int ra0 = g0 >> 2, qa0 = (g0 & 3) * 16;
    const int ra1 = g1 >> 2, qa1 = (g1 & 3) * 16;
    const char* gA0 = (const char*)(Acat + (size_t)(m0 + ra0) * cKC) + qa0;
    const char* gA1 = (const char*)(Acat + (size_t)(m0 + ra1) * cKC) + qa1;
    const char* gB0 = (const char*)(Wcat + (size_t)(n0 + ra0) * cKC) + qa0;
    const char* gB1 = (const char*)(Wcat + (size_t)(n0 + ra1) * cKC) + qa1;
    unsigned dA0 = smem_u32(sm) + ra0 * STRD + qa0;
    unsigned dA1 = smem_u32(sm) + ra1 * STRD + qa1;
    unsigned dB0 = dA0 + 128 * STRD, dB1 = dA1 + 128 * STRD;
    const unsigned bufsz = 2 * 128 * STRD;

    unsigned laA = smem_u32(sm) + (warp_m + (lane & 15)) * STRD + (lane >> 4) * 16;
    unsigned laB = smem_u32(sm) + 128 * STRD + (warp_n + (lane & 7)) * STRD + ((lane >> 3) & 1) * 16;

    asm volatile("cp.async.cg.shared.global [%0], [%1], 16;" :: "r"(dA0), "l"(gA0));
    asm volatile("cp.async.cg.shared.global [%0], [%1], 16;" :: "r"(dA1), "l"(gA1));
    asm volatile("cp.async.cg.shared.global [%0], [%1], 16;" :: "r"(dB0), "l"(gB0));
    asm volatile("cp.async.cg.shared.global [%0], [%1], 16;" :: "r"(dB1), "l"(gB1));
    asm volatile("cp.async.commit_group;");

    int buf = 0;
    for (int c = 0; c < 96; c++) {
        if (c + 1 < 96) {
            size_t go = (size_t)(c + 1) * 64;
            unsigned so = (buf ^ 1) * bufsz;
            asm volatile("cp.async.cg.shared.global [%0], [%1], 16;" :: "r"(dA0 + so), "l"(gA0 + go));
            asm volatile("cp.async.cg.shared.global [%0], [%1], 16;" :: "r"(dA1 + so), "l"(gA1 + go));
            asm volatile("cp.async.cg.shared.global [%0], [%1], 16;" :: "r"(dB0 + so), "l"(gB0 + go));
            asm volatile("cp.async.cg.shared.global [%0], [%1], 16;" :: "r"(dB1 + so), "l"(gB1 + go));
            asm volatile("cp.async.commit_group;");
            asm volatile("cp.async.wait_group 1;");
        } else {
            asm volatile("cp.async.wait_group 0;");
        }
        __syncthreads();

        unsigned so = buf * bufsz;
        #pragma unroll
        for (int ks = 0; ks < 2; ks++) {
            uint32_t af[4][4], bf[4][2];
            #pragma unroll
            for (int mf = 0; mf < 4; mf++) {
                unsigned ad = laA + so + mf * (16 * STRD) + ks * 32;
                asm volatile("ldmatrix.sync.aligned.m8n8.x4.shared.b16 {%0,%1,%2,%3}, [%4];"
                    : "=r"(af[mf][0]), "=r"(af[mf][1]), "=r"(af[mf][2]), "=r"(af[mf][3]) : "r"(ad));
            }
            #pragma unroll
            for (int nf = 0; nf < 4; nf++) {
                unsigned bd = laB + so + nf * (8 * STRD) + ks * 32;
                asm volatile("ldmatrix.sync.aligned.m8n8.x2.shared.b16 {%0,%1}, [%2];"
                    : "=r"(bf[nf][0]), "=r"(bf[nf][1]) : "r"(bd));
            }
            #pragma unroll
            for (int mf = 0; mf < 4; mf++)
                #pragma unroll
                for (int nf = 0; nf < 4; nf++) {
                    asm volatile(
                        "mma.sync.aligned.m16n8k16.row.col.f32.bf16.bf16.f32 "
                        "{%0,%1,%2,%3}, {%4,%5,%6,%7}, {%8,%9}, {%0,%1,%2,%3};"
                        : "+f"(acc[mf][nf][0]), "+f"(acc[mf][nf][1]),
                          "+f"(acc[mf][nf][2]), "+f"(acc[mf][nf][3])
                        : "r"(af[mf][0]), "r"(af[mf][1]), "r"(af[mf][2]), "r"(af[mf][3]),
                          "r"(bf[nf][0]), "r"(bf[nf][1]));
                }
        }
        __syncthreads();
        buf ^= 1;
    }

    #pragma unroll
    for (int mf = 0; mf < 4; mf++) {
        int mbase = m0 + warp_m + mf * 16 + (lane >> 2);
        int mA = mbase, mB = mbase + 8;
        size_t rbA = (size_t)((mA & 31) * 64 + (mA >> 5)) * cV;
        size_t rbB = (size_t)((mB & 31) * 64 + (mB >> 5)) * cV;
        #pragma unroll
        for (int nf = 0; nf < 4; nf++) {
            int n = n0 + warp_n + nf * 8 + (lane & 3) * 2;
            float2 bb = *(const float2*)&bout[n];
            float2 v0 = {acc[mf][nf][0] + bb.x, acc[mf][nf][1] + bb.y};
            float2 v1 = {acc[mf][nf][2] + bb.x, acc[mf][nf][3] + bb.y};
            *(float2*)&out[rbA + n] = v0;
            *(float2*)&out[rbB + n] = v1;
        }
    }
}

// ============ HMMA prep GEMM
__global__ __launch_bounds__(256, 2)
void k_prep_mma(const __nv_bfloat16* __restrict__ Acat,
                const __nv_bfloat16* __restrict__ Wcat,
                const float* __restrict__ bi, const float* __restrict__ bh,
                float* __restrict__ O)
{
    __shared__ char sm[2][2 * 128 * STRD];
    const int tid = threadIdx.x, wid = tid >> 5, lane = tid & 31;
    const int m0 = blockIdx.x * 128, n0 = blockIdx.y * 128;
    const int warp_m = (wid & 1) * 64, warp_n = (wid >> 1) * 32;

    float acc[4][4][4];
    #pragma unroll
    for (int a = 0; a < 4; a++)
        #pragma unroll
        for (int b = 0; b < 4; b++)
            #pragma unroll
            for (int d = 0; d < 4; d++) acc[a][b][d] = 0.f;

    const int g0 = tid, g1 = tid + 256;
    const int ra0 = g0 >> 2, qa0 = (g0 & 3) * 16;
    const int ra1 = g1 >> 2, qa1 = (g1 & 3) * 16;
    const char* gA0 = (const char*)(Acat + (size_t)(m0 + ra0) * 1536) + qa0;
    const char* gA1 = (const char*)(Acat + (size_t)(m0 + ra1) * 1536) + qa1;
    const char* gB0 = (const char*)(Wcat + (size_t)(n0 + ra0) * 1536) + qa0;
    const char* gB1 = (const char*)(Wcat + (size_t)(n0 + ra1) * 1536) + qa1;
    unsigned dA0 = smem_u32(sm) + ra0 * STRD + qa0;
    unsigned dA1 = smem_u32(sm) + ra1 * STRD + qa1;
    unsigned dB0 = dA0 + 128 * STRD, dB1 = dA1 + 128 * STRD;
    const unsigned bufsz = 2 * 128 * STRD;

    unsigned laA = smem_u32(sm) + (warp_m + (lane & 15)) * STRD + (lane >> 4) * 16;
    unsigned laB = smem_u32(sm) + 128 * STRD + (warp_n + (lane & 7)) * STRD + ((lane >> 3) & 1) * 16;

    asm volatile("cp.async.cg.shared.global [%0], [%1], 16;" :: "r"(dA0), "l"(gA0));
    asm volatile("cp.async.cg.shared.global [%0], [%1], 16;" :: "r"(dA1), "l"(gA1));
    asm volatile("cp.async.cg.shared.global [%0], [%1], 16;" :: "r"(dB0), "l"(gB0));
    asm volatile("cp.async.cg.shared.global [%0], [%1], 16;" :: "r"(dB1), "l"(gB1));
    asm volatile("cp.async.commit_group;");

    int buf = 0;
    for (int c = 0; c < 48; c++) {
        if (c + 1 < 48) {
            size_t go = (size_t)(c + 1) * 64;
            unsigned so = (buf ^ 1) * bufsz;
            asm volatile("cp.async.cg.shared.global [%0], [%1], 16;" :: "r"(dA0 + so), "l"(gA0 + go));
            asm volatile("cp.async.cg.shared.global [%0], [%1], 16;" :: "r"(dA1 + so), "l"(gA1 + go));
            asm volatile("cp.async.cg.shared.global [%0], [%1], 16;" :: "r"(dB0 + so), "l"(gB0 + go));
            asm volatile("cp.async.cg.shared.global [%0], [%1], 16;" :: "r"(dB1 + so), "l"(gB1 + go));
            asm volatile("cp.async.commit_group;");
            asm volatile("cp.async.wait_group 1;");
        } else {
            asm volatile("cp.async.wait_group 0;");
        }
        __syncthreads();

        unsigned so = buf * bufsz;
        #pragma unroll
        for (int ks = 0; ks < 2; ks++) {
            uint32_t af[4][4], bf[4][2];
            #pragma unroll
            for (int mf = 0; mf < 4; mf++) {
                unsigned ad = laA + so + mf * (16 * STRD) + ks * 32;
                asm volatile("ldmatrix.sync.aligned.m8n8.x4.shared.b16 {%0,%1,%2,%3}, [%4];"
                    : "=r"(af[mf][0]), "=r"(af[mf][1]), "=r"(af[mf][2]), "=r"(af[mf][3]) : "r"(ad));
            }
            #pragma unroll
            for (int nf = 0; nf < 4; nf++) {
                unsigned bd = laB + so + nf * (8 * STRD) + ks * 32;
                asm volatile("ldmatrix.sync.aligned.m8n8.x2.shared.b16 {%0,%1}, [%2];"
                    : "=r"(bf[nf][0]), "=r"(bf[nf][1]) : "r"(bd));
            }
            #pragma unroll
            for (int mf = 0; mf < 4; mf++)
                #pragma unroll
                for (int nf = 0; nf < 4; nf++) {
                    asm volatile(
                        "mma.sync.aligned.m16n8k16.row.col.f32.bf16.bf16.f32 "
                        "{%0,%1,%2,%3}, {%4,%5,%6,%7}, {%8,%9}, {%0,%1,%2,%3};"
                        : "+f"(acc[mf][nf][0]), "+f"(acc[mf][nf][1]),
                          "+f"(acc[mf][nf][2]), "+f"(acc[mf][nf][3])
                        : "r"(af[mf][0]), "r"(af[mf][1]), "r"(af[mf][2]), "r"(af[mf][3]),
                          "r"(bf[nf][0]), "r"(bf[nf][1]));
                }
        }
        __syncthreads();
        buf ^= 1;
    }

    #pragma unroll
    for (int mf = 0; mf < 4; mf++) {
        int mA = m0 + warp_m + mf * 16 + (lane >> 2);
        int mB = mA + 8;
        #pragma unroll
        for (int nf = 0; nf < 4; nf++) {
            int n = n0 + warp_n + nf * 8 + (lane & 3) * 2;
            float2 b1 = *(const float2*)&bi[n];
            float2 b2 = *(const float2*)&bh[n];
            float2 v0 = {acc[mf][nf][0] + b1.x + b2.x, acc[mf][nf][1] + b1.y + b2.y};
            float2 v1 = {acc[mf][nf][2] + b1.x + b2.x, acc[mf][nf][3] + b1.y + b2.y};
            *(float2*)&O[(size_t)mA * cG + n] = v0;
            *(float2*)&O[(size_t)mB * cG + n] = v1;
        }
    }
}

// ============ FUSED recurrent step (encoder, both dirs): GEMM(32x64x3072) + LSTM
// Weights gate-interleaved (row 4j+g). CTA = (n-tile 64 permuted rows, dir).
__global__ __launch_bounds__(256, 2)
void k_fstep_enc(const __nv_bfloat16* __restrict__ hinF, const __nv_bfloat16* __restrict__ hinB,
                 const __nv_bfloat16* __restrict__ WF, const __nv_bfloat16* __restrict__ WB,
                 const float* __restrict__ GxF, const float* __restrict__ GxB,
                 float* __restrict__ ccF, float* __restrict__ ccB,
                 float* __restrict__ hhF, float* __restrict__ hhB,
                 float* __restrict__ ssF, float* __restrict__ ssB,
                 __nv_bfloat16* __restrict__ houtF, __nv_bfloat16* __restrict__ houtB)
{
    __shared__ char sm[2][(32 + 64) * STRD];
    const int dir = blockIdx.y;
    const __nv_bfloat16* hin = dir ? hinB : hinF;
    const __nv_bfloat16* W   = dir ? WB : WF;
    const float* Gx = dir ? GxB : GxF;
    float* cP = dir ? ccB : ccF;
    float* hP = dir ? hhB : hhF;
    float* sP = dir ? ssB : ssF;
    __nv_bfloat16* hout = dir ? houtB : houtF;

    const int tid = threadIdx.x, wid = tid >> 5, lane = tid & 31;
    const int n0 = blockIdx.x * 64;

    float acc[2][4];
    #pragma unroll
    for (int a = 0; a < 2; a++)
        #pragma unroll
        for (int d = 0; d < 4; d++) acc[a][d] = 0.f;

    const int ra = tid >> 2, q = (tid & 3) * 16;
    const char* gA = (const char*)hin + (size_t)ra * 6144 + q;           // ra<32 when tid<128
    const char* gB = (const char*)W + (size_t)(n0 + ra) * 6144 + q;      // ra in 0..63
    unsigned base = smem_u32(sm);
    unsigned dA = base + ra * STRD + q;
    unsigned dB = base + (32 + ra) * STRD + q;
    const unsigned bufsz = (32 + 64) * STRD;

    unsigned laA = base + (lane & 15) * STRD + (lane >> 4) * 16;
    unsigned laB = base + 32 * STRD + (wid * 8 + (lane & 7)) * STRD + ((lane >> 3) & 1) * 16;

    if (tid < 128)
        asm volatile("cp.async.cg.shared.global [%0], [%1], 16;" :: "r"(dA), "l"(gA));
    asm volatile("cp.async.cg.shared.global [%0], [%1], 16;" :: "r"(dB), "l"(gB));
    asm volatile("cp.async.commit_group;");

    int buf = 0;
    for (int c = 0; c < 96; c++) {
        if (c + 1 < 96) {
            size_t go = (size_t)(c + 1) * 64;
            unsigned so = (buf ^ 1) * bufsz;
            if (tid < 128)
                asm volatile("cp.async.cg.shared.global [%0], [%1], 16;" :: "r"(dA + so), "l"(gA + go));
            asm volatile("cp.async.cg.shared.global [%0], [%1], 16;" :: "r"(dB + so), "l"(gB + go));
            asm volatile("cp.async.commit_group;");
            asm volatile("cp.async.wait_group 1;");
        } else {
            asm volatile("cp.async.wait_group 0;");
        }
        __syncthreads();

        unsigned so = buf * bufsz;
        #pragma unroll
        for (int ks = 0; ks < 2; ks++) {
            uint32_t af[2][4], bf[2];
            #pragma unroll
            for (int mf = 0; mf < 2; mf++) {
                unsigned ad = laA + so + mf * (16 * STRD) + ks * 32;
                asm volatile("ldmatrix.sync.aligned.m8n8.x4.shared.b16 {%0,%1,%2,%3}, [%4];"
                    : "=r"(af[mf][0]), "=r"(af[mf][1]), "=r"(af[mf][2]), "=r"(af[mf][3]) : "r"(ad));
            }
            unsigned bd = laB + so + ks * 32;
            asm volatile("ldmatrix.sync.aligned.m8n8.x2.shared.b16 {%0,%1}, [%2];"
                : "=r"(bf[0]), "=r"(bf[1]) : "r"(bd));
            #pragma unroll
            for (int mf = 0; mf < 2; mf++) {
                asm volatile(
                    "mma.sync.aligned.m16n8k16.row.col.f32.bf16.bf16.f32 "
                    "{%0,%1,%2,%3}, {%4,%5,%6,%7}, {%8,%9}, {%0,%1,%2,%3};"
                    : "+f"(acc[mf][0]), "+f"(acc[mf][1]), "+f"(acc[mf][2]), "+f"(acc[mf][3])
                    : "r"(af[mf][0]), "r"(af[mf][1]), "r"(af[mf][2]), "r"(af[mf][3]),
                      "r"(bf[0]), "r"(bf[1]));
            }
        }
        __syncthreads();
        buf ^= 1;
    }

    // accumulators -> smem (rows = batch, cols = permuted local gate cols)
    float* sOut = (float*)&sm[0][0];   // 32 x 66
    #pragma unroll
    for (int mf = 0; mf < 2; mf++) {
        int row = mf * 16 + (lane >> 2);
        int col = wid * 8 + (lane & 3) * 2;
        sOut[row * 66 + col]       = acc[mf][0];
        sOut[row * 66 + col + 1]   = acc[mf][1];
        sOut[(row+8) * 66 + col]   = acc[mf][2];
        sOut[(row+8) * 66 + col+1] = acc[mf][3];
    }
    __syncthreads();

    // LSTM: 512 (b, j) elements; col layout 4*jl + g
    #pragma unroll
    for (int k = 0; k < 2; k++) {
        int e = tid + k * 256;
        int b = e >> 4, jl = e & 15;
        int j = blockIdx.x * 16 + jl;
        float gi = sOut[b * 66 + jl * 4 + 0] + Gx[b * cG + j];
        float gf = sOut[b * 66 + jl * 4 + 1] + Gx[b * cG + 1024 + j];
        float gg = sOut[b * 66 + jl * 4 + 2] + Gx[b * cG + 2048 + j];
        float go = sOut[b * 66 + jl * 4 + 3] + Gx[b * cG + 3072 + j];
        int u = b * cH + j;
        float c = sigf(gf) * cP[u] + sigf(gi) * tanhf(gg);
        cP[u] = c;
        float h = sigf(go) * tanhf(c);
        hP[u] = h;
        sP[u] += h;
        __nv_bfloat16 hh, hl; bf16split(h, hh, hl);
        __nv_bfloat16* hcp = hout + b * 3072;
        hcp[j] = hh; hcp[1024 + j] = hl; hcp[2048 + j] = hh;
    }
}

// ============ FUSED recurrent step (decoder)
__global__ __launch_bounds__(256, 2)
void k_fstep_dec(const __nv_bfloat16* __restrict__ hin, const __nv_bfloat16* __restrict__ W,
                 const float* __restrict__ Gx, float* __restrict__ cD,
                 float* __restrict__ hdec_t, __nv_bfloat16* __restrict__ hout)
{
    __shared__ char sm[2][(32 + 64) * STRD];
    const int tid = threadIdx.x, wid = tid >> 5, lane = tid & 31;
    const int n0 = blockIdx.x * 64;

    float acc[2][4];
    #pragma unroll
    for (int a = 0; a < 2; a++)
        #pragma unroll
        for (int d = 0; d < 4; d++) acc[a][d] = 0.f;

    const int ra = tid >> 2, q = (tid & 3) * 16;
    const char* gA = (const char*)hin + (size_t)ra * 6144 + q;
    const char* gB = (const char*)W + (size_t)(n0 + ra) * 6144 + q;
    unsigned base = smem_u32(sm);
    unsigned dA = base + ra * STRD + q;
    unsigned dB = base + (32 + ra) * STRD + q;
    const unsigned bufsz = (32 + 64) * STRD;

    unsigned laA = base + (lane & 15) * STRD + (lane >> 4) * 16;
    unsigned laB = base + 32 * STRD + (wid * 8 + (lane & 7)) * STRD + ((lane >> 3) & 1) * 16;

    if (tid < 128)
        asm volatile("cp.async.cg.shared.global [%0], [%1], 16;" :: "r"(dA), "l"(gA));
    asm volatile("cp.async.cg.shared.global [%0], [%1], 16;" :: "r"(dB), "l"(gB));
    asm volatile("cp.async.commit_group;");

    int buf = 0;
    for (int c = 0; c < 96; c++) {
        if (c + 1 < 96) {
            size_t go = (size_t)(c + 1) * 64;
            unsigned so = (buf ^ 1) * bufsz;
            if (tid < 128)
                asm volatile("cp.async.cg.shared.global [%0], [%1], 16;" :: "r"(dA + so), "l"(gA + go));
            asm volatile("cp.async.cg.shared.global [%0], [%1], 16;" :: "r"(dB + so), "l"(gB + go));
            asm volatile("cp.async.commit_group;");
            asm volatile("cp.async.wait_group 1;");
        } else {
            asm volatile("cp.async.wait_group 0;");
        }
        __syncthreads();

        unsigned so = buf * bufsz;
        #pragma unroll
        for (int ks = 0; ks < 2; ks++) {
            uint32_t af[2][4], bf[2];
            #pragma unroll
            for (int mf = 0; mf < 2; mf++) {
                unsigned ad = laA + so + mf * (16 * STRD) + ks * 32;
                asm volatile("ldmatrix.sync.aligned.m8n8.x4.shared.b16 {%0,%1,%2,%3}, [%4];"
                    : "=r"(af[mf][0]), "=r"(af[mf][1]), "=r"(af[mf][2]), "=r"(af[mf][3]) : "r"(ad));
            }
            unsigned bd = laB + so + ks * 32;
            asm volatile("ldmatrix.sync.aligned.m8n8.x2.shared.b16 {%0,%1}, [%2];"
                : "=r"(bf[0]), "=r"(bf[1]) : "r"(bd));
            #pragma unroll
            for (int mf = 0; mf < 2; mf++) {
                asm volatile(
                    "mma.sync.aligned.m16n8k16.row.col.f32.bf16.bf16.f32 "
                    "{%0,%1,%2,%3}, {%4,%5,%6,%7}, {%8,%9}, {%0,%1,%2,%3};"
                    : "+f"(acc[mf][0]), "+f"(acc[mf][1]), "+f"(acc[mf][2]), "+f"(acc[mf][3])
                    : "r"(af[mf][0]), "r"(af[mf][1]), "r"(af[mf][2]), "r"(af[mf][3]),
                      "r"(bf[0]), "r"(bf[1]));
            }
        }
        __syncthreads();
        buf ^= 1;
    }

    float* sOut = (float*)&sm[0][0];
    #pragma unroll
    for (int mf = 0; mf < 2; mf++) {
        int row = mf * 16 + (lane >> 2);
        int col = wid * 8 + (lane & 3) * 2;
        sOut[row * 66 + col]       = acc[mf][0];
        sOut[row * 66 + col + 1]   = acc[mf][1];
        sOut[(row+8) * 66 + col]   = acc[mf][2];
        sOut[(row+8) * 66 + col+1] = acc[mf][3];
    }
    __syncthreads();

    #pragma unroll
    for (int k = 0; k < 2; k++) {
        int e = tid + k * 256;
        int b = e >> 4, jl = e & 15;
        int j = blockIdx.x * 16 + jl;
        float gi = sOut[b * 66 + jl * 4 + 0] + Gx[b * cG + j];
        float gf = sOut[b * 66 + jl * 4 + 1] + Gx[b * cG + 1024 + j];
        float gg = sOut[b * 66 + jl * 4 + 2] + Gx[b * cG + 2048 + j];
        float go = sOut[b * 66 + jl * 4 + 3] + Gx[b * cG + 3072 + j];
        int u = b * cH + j;
        float c = sigf(gf) * cD[u] + sigf(gi) * tanhf(gg);
        cD[u] = c;
        float h = sigf(go) * tanhf(c);
        hdec_t[u] = h;
        __nv_bfloat16 hh, hl; bf16split(h, hh, hl);
        __nv_bfloat16* hcp = hout + b * 3072;
        hcp[j] = hh; hcp[1024 + j] = hl; hcp[2048 + j] = hh;
    }
}

__global__ void k_zero(float* __restrict__ p, int n)
{
    int i = blockIdx.x * 256 + threadIdx.x;
    if (i < n) p[i] = 0.f;
}

__global__ void k_initdec(const float* __restrict__ hf, const float* __restrict__ hb,
                          const float* __restrict__ cf, const float* __restrict__ cbp,
                          float* __restrict__ cd, __nv_bfloat16* __restrict__ hdc)
{
    int u = blockIdx.x * 256 + threadIdx.x;
    float h = hf[u] + hb[u];
    cd[u] = cf[u] + cbp[u];
    int b = u >> 10, j = u & 1023;
    __nv_bfloat16 hh, hl; bf16split(h, hh, hl);
    __nv_bfloat16* hcp = hdc + b * 3072;
    hcp[j] = hh; hcp[1024 + j] = hl; hcp[2048 + j] = hh;
}

// ============ decoder constant bias partials (fp32, small)
__global__ __launch_bounds__(256) void k_decbias(
    const float* __restrict__ sumf, const float* __restrict__ sumb,
    const float* __restrict__ Wc, float* __restrict__ parts)
{
    __shared__ float As[16][33];
    __shared__ float Bs[16][128];
    const int tid = threadIdx.x, n0 = blockIdx.x * 128;
    const int kn = 2048 / gridDim.z, kbeg = blockIdx.z * kn;
    const int tx = tid & 31, ty = tid >> 5;
    float acc[4][4];
    #pragma unroll
    for (int i = 0; i < 4; i++)
        #pragma unroll
        for (int j = 0; j < 4; j++) acc[i][j] = 0.f;

    for (int k0 = kbeg; k0 < kbeg + kn; k0 += 16) {
        if (tid < 128) {
            int r = tid >> 2, c4 = (tid & 3) << 2;
            int k = k0 + c4;
            const float* src = (k < 1024) ? &sumf[r*cH + k] : &sumb[r*cH + k - 1024];
            float4 v = *(const float4*)src;
            As[c4+0][r]=v.x; As[c4+1][r]=v.y; As[c4+2][r]=v.z; As[c4+3][r]=v.w;
        }
        #pragma unroll
        for (int L = 0; L < 2; L++) {
            int flat = tid + (L << 8);
            int r = flat >> 2, c4 = (flat & 3) << 2;
            float4 v = *(const float4*)&Wc[(size_t)(n0 + r) * 3072 + 1024 + k0 + c4];
            Bs[c4+0][r]=v.x; Bs[c4+1][r]=v.y; Bs[c4+2][r]=v.z; Bs[c4+3][r]=v.w;
        }
        __syncthreads();
        #pragma unroll
        for (int kk = 0; kk < 16; kk++) {
            float a0=As[kk][ty*4+0], a1=As[kk][ty*4+1], a2=As[kk][ty*4+2], a3=As[kk][ty*4+3];
            float4 b = *(const float4*)&Bs[kk][tx*4];
            acc[0][0]+=a0*b.x; acc[0][1]+=a0*b.y; acc[0][2]+=a0*b.z; acc[0][3]+=a0*b.w;
            acc[1][0]+=a1*b.x; acc[1][1]+=a1*b.y; acc[1][2]+=a1*b.z; acc[1][3]+=a1*b.w;
            acc[2][0]+=a2*b.x; acc[2][1]+=a2*b.y; acc[2][2]+=a2*b.z; acc[2][3]+=a2*b.w;
            acc[3][0]+=a3*b.x; acc[3][1]+=a3*b.y; acc[3][2]+=a3*b.z; acc[3][3]+=a3*b.w;
        }
        __syncthreads();
    }
    float* out = parts + (size_t)blockIdx.z * 32768;
    #pragma unroll
    for (int i = 0; i < 4; i++) {
        int b = ty*4 + i;
        #pragma unroll
        for (int j = 0; j < 4; j++)
            out[b*cH + n0 + tx*4 + j] = acc[i][j];
    }
}

__global__ void k_redbias(const float* __restrict__ parts, const float* __restrict__ bc,
                          float* __restrict__ decb)
{
    int u = blockIdx.x * 256 + threadIdx.x;
    float a = bc[u & 1023];
    #pragma unroll
    for (int z = 0; z < 8; z++) a += parts[z * 32768 + u];
    decb[u] = a;
}

// ============ outs = tanh(Hdec @ Wc[:, :1024].T + decb[b])  (fp32, f32x2)
__global__ __launch_bounds__(256, 2) void k_outs(
    const float* __restrict__ A, const float* __restrict__ Wc,
    const float* __restrict__ decb, float* __restrict__ O)
{
    __shared__ float As[16][128];
    __shared__ float Bs[16][128];
    const int m0 = blockIdx.x * 128, n0 = blockIdx.y * 128;
    const int tid = threadIdx.x, tx = tid & 15, ty = tid >> 4;
    u64 acc2[8][4];
    #pragma unroll
    for (int i = 0; i < 8; i++)
        #pragma unroll
        for (int j = 0; j < 4; j++) acc2[i][j] = 0ull;

    for (int k0 = 0; k0 < cH; k0 += 16) {
        #pragma unroll
        for (int L = 0; L < 2; L++) {
            int flat = tid + (L << 8);
            int r = flat >> 2, c4 = (flat & 3) << 2;
            float4 v = *(const float4*)&A[(size_t)(m0 + r) * cH + k0 + c4];
            As[c4+0][r]=v.x; As[c4+1][r]=v.y; As[c4+2][r]=v.z; As[c4+3][r]=v.w;
        }
        #pragma unroll
        for (int L = 0; L < 2; L++) {
            int flat = tid + (L << 8);
            int r = flat >> 2, c4 = (flat & 3) << 2;
            float4 v = *(const float4*)&Wc[(size_t)(n0 + r) * 3072 + k0 + c4];
            Bs[c4+0][r]=v.x; Bs[c4+1][r]=v.y; Bs[c4+2][r]=v.z; Bs[c4+3][r]=v.w;
        }
        __syncthreads();
        #pragma unroll
        for (int kk = 0; kk < 16; kk++) {
            float4 a0 = *(const float4*)&As[kk][ty*8];
            float4 a1 = *(const float4*)&As[kk][ty*8+4];
            u64 aa[8] = {splat2(a0.x),splat2(a0.y),splat2(a0.z),splat2(a0.w),
                         splat2(a1.x),splat2(a1.y),splat2(a1.z),splat2(a1.w)};
            ulonglong2 b01 = *(const ulonglong2*)&Bs[kk][tx*8];
            ulonglong2 b23 = *(const ulonglong2*)&Bs[kk][tx*8+4];
            u64 bb[4] = {b01.x, b01.y, b23.x, b23.y};
            #pragma unroll
            for (int i = 0; i < 8; i++)
                #pragma unroll
                for (int j = 0; j < 4; j++) fma2(acc2[i][j], aa[i], bb[j]);
        }
        __syncthreads();
    }
    #pragma unroll
    for (int i = 0; i < 8; i++) {
        int m = m0 + ty*8 + i;
        #pragma unroll
        for (int j = 0; j < 4; j++) {
            int n = n0 + tx*8 + j*2;
            float2 v = unpk(acc2[i][j]);
            O[(size_t)m*cH + n]     = tanhf(v.x + decb[(m & 31) * cH + n]);
            O[(size_t)m*cH + n + 1] = tanhf(v.y + decb[(m & 31) * cH + n + 1]);
        }
    }
}

// ============ in-place log_softmax over V + argmax
__global__ void k_softmax(float* __restrict__ out, float* __restrict__ preds, int write_preds)
{
    int r = blockIdx.x;
    float* row = out + (size_t)r * cV;
    int tid = threadIdx.x;
    __shared__ float sm[256];
    __shared__ int   si[256];
    float m = -1e30f; int mi = 0;
    for (int v = tid; v < cV; v += 256) {
        float x = row[v];
        if (x > m) { m = x; mi = v; }
    }
    sm[tid] = m; si[tid] = mi;
    __syncthreads();
    for (int s = 128; s > 0; s >>= 1) {
        if (tid < s) {
            float o = sm[tid+s]; int oi = si[tid+s];
            if (o > sm[tid] || (o == sm[tid] && oi < si[tid])) { sm[tid] = o; si[tid] = oi; }
        }
        __syncthreads();
    }
    float rowmax = sm[0];
    int rowarg = si[0];
    float acc = 0.f;
    for (int v = tid; v < cV; v += 256) acc += expf(row[v] - rowmax);
    sm[tid] = acc;
    __syncthreads();
    for (int s = 128; s > 0; s >>= 1) {
        if (tid < s) sm[tid] += sm[tid+s];
        __syncthreads();
    }
    float lse = rowmax + logf(sm[0]);
    for (int v = tid; v < cV; v += 256) row[v] -= lse;
    if (tid == 0 && write_preds) preds[r] = (float)rowarg;
}

extern "C" void kernel_launch(void* const* d_in, const int* in_sizes, int n_in,
                              void* d_out, int out_size)
{
    const int*   inputs  = (const int*)d_in[0];
    const int*   targets = (const int*)d_in[1];
    const float* emb_src = (const float*)d_in[2];
    const float* Wih_f = (const float*)d_in[3];
    const float* Whh_f = (const float*)d_in[4];
    const float* bih_f = (const float*)d_in[5];
    const float* bhh_f = (const float*)d_in[6];
    const float* Wih_b = (const float*)d_in[7];
    const float* Whh_b = (const float*)d_in[8];
    const float* bih_b = (const float*)d_in[9];
    const float* bhh_b = (const float*)d_in[10];
    const float* emb_tgt = (const float*)d_in[11];
    const float* Wih_d = (const float*)d_in[12];
    const float* Whh_d = (const float*)d_in[13];
    const float* bih_d = (const float*)d_in[14];
    const float* bhh_d = (const float*)d_in[15];
    /* d_in[16] = Wattn: unused (softmax over singleton axis) */
    const float* Wc   = (const float*)d_in[17];
    const float* bc   = (const float*)d_in[18];
    const float* Wout = (const float*)d_in[19];
    const float* bout = (const float*)d_in[20];
    float* out = (float*)d_out;

    float* scr = nullptr;
    cudaGetSymbolAddress((void**)&scr, g_scr);
    __nv_bfloat16* Acat = nullptr; cudaGetSymbolAddress((void**)&Acat, g_Acat);
    __nv_bfloat16* Wcat = nullptr; cudaGetSymbolAddress((void**)&Wcat, g_Wcat);
    __nv_bfloat16* WihC = nullptr; cudaGetSymbolAddress((void**)&WihC, g_WihC);
    __nv_bfloat16* WhhC = nullptr; cudaGetSymbolAddress((void**)&WhhC, g_WhhC);
    __nv_bfloat16* AE = nullptr; cudaGetSymbolAddress((void**)&AE, g_AE);
    __nv_bfloat16* AD = nullptr; cudaGetSymbolAddress((void**)&AD, g_AD);
    __nv_bfloat16* hc = nullptr; cudaGetSymbolAddress((void**)&hc, g_hc);

    __nv_bfloat16* WihC0 = WihC;
    __nv_bfloat16* WihC1 = WihC + (size_t)cG * 1536;
    __nv_bfloat16* WihC2 = WihC + 2 * (size_t)cG * 1536;
    __nv_bfloat16* WhhP0 = WhhC;
    __nv_bfloat16* WhhP1 = WhhC + (size_t)cG * 3072;
    __nv_bfloat16* WhhP2 = WhhC + 2 * (size_t)cG * 3072;
    __nv_bfloat16* hcF[2] = {hc,            hc + 98304};
    __nv_bfloat16* hcB[2] = {hc + 196608,   hc + 294912};
    __nv_bfloat16* hcD[2] = {hc + 393216,   hc + 491520};

    float* GF    = scr + OFF_GF;
    float* GB    = scr + OFF_GB;
    float* GD    = scr + OFF_GD;
    float* GATES = scr + OFF_GATES;
    float* HF = scr + OFF_HF;  float* CF = scr + OFF_CF;
    float* HB = scr + OFF_HB;  float* CBv = scr + OFF_CB;
    float* SF = scr + OFF_SUMF; float* SB = scr + OFF_SUMB;
    float* CD = scr + OFF_CD;
    float* DECB = scr + OFF_DECB;
    float* HDEC = scr + OFF_HDEC;
    float* OUTS = scr + OFF_OUTS;

    // weight splits (Whh gate-interleaved for fused steps)
    k_splitW<<<64000, 256>>>(Wout, Wcat, cV);
    k_splitWhhP<<<8192, 256>>>(Whh_f, WhhP0);
    k_splitWhhP<<<8192, 256>>>(Whh_b, WhhP1);
    k_splitWhhP<<<8192, 256>>>(Whh_d, WhhP2);
    k_splitW512<<<4096, 256>>>(Wih_f, WihC0, cG);
    k_splitW512<<<4096, 256>>>(Wih_b, WihC1, cG);
    k_splitW512<<<4096, 256>>>(Wih_d, WihC2, cG);
    k_gather512<<<2048, 256>>>(inputs, emb_src, AE);
    k_gather512<<<2048, 256>>>(targets, emb_tgt, AD);

    // batched gate pre-activations (HMMA)
    k_prep_mma<<<dim3(16, 32), 256>>>(AE, WihC0, bih_f, bhh_f, GF);
    k_prep_mma<<<dim3(16, 32), 256>>>(AE, WihC1, bih_b, bhh_b, GB);
    k_prep_mma<<<dim3(16, 32), 256>>>(AD, WihC2, bih_d, bhh_d, GD);
    k_zero<<<768, 256>>>(HF, 196608);
    // FULL hc clear: 6 bufs x 98304 bf16 = 294912 floats (replay determinism)
    k_zero<<<1152, 256>>>((float*)hc, 294912);

    // encoder: one fused kernel per step (reads hc[t&1], writes hc[(t+1)&1])
    for (int t = 0; t < cS; t++) {
        int a = t & 1, b = a ^ 1;
        k_fstep_enc<<<dim3(64, 2), 256>>>(hcF[a], hcB[a], WhhP0, WhhP1,
                                          GF + (size_t)t * 131072,
                                          GB + (size_t)(cS - 1 - t) * 131072,
                                          CF, CBv, HF, HB, SF, SB,
                                          hcF[b], hcB[b]);
    }

    k_initdec<<<128, 256>>>(HF, HB, CF, CBv, CD, hcD[0]);
    k_decbias<<<dim3(8, 1, 8), 256>>>(SF, SB, Wc, GATES);
    k_redbias<<<128, 256>>>(GATES, bc, DECB);

    // decoder: fused steps
    for (int t = 0; t < cT; t++) {
        int a = t & 1, b = a ^ 1;
        k_fstep_dec<<<64, 256>>>(hcD[a], WhhP2, GD + (size_t)t * 131072,
                                 CD, HDEC + (size_t)t * 32768, hcD[b]);
    }

    k_outs<<<dim3(16, 8), 256>>>(HDEC, Wc, DECB, OUTS);

    // tensor-core logits
    k_splitA<<<4096, 256>>>(OUTS, Acat, 2048);
    k_logits_mma<<<dim3(16, 250), 256>>>(Acat, Wcat, bout, out);

    int write_preds = (out_size >= cB * cT * cV + cB * cT) ? 1 : 0;
    k_softmax<<<2048, 256>>>(out, out + (size_t)cB * cT * cV, write_preds);
}

// round 15
// speedup vs baseline: 1.3504x; 1.3504x over previous
#include <cuda_runtime.h>
#include <cuda_bf16.h>
#include <math.h>
#include <stdint.h>

#define cB 32
#define cS 64
#define cT 64
#define cE 512
#define cH 1024
#define cG 4096
#define cV 32000
#define cKC 3072

// ---- scratch layout (float offsets) ----
#define OFF_GF      0ull
#define OFF_GB      8388608ull
#define OFF_GD      16777216ull
#define OFF_GATES   25165824ull   // 4 slots x 131072
#define OFF_HF      25690112ull
#define OFF_CF      25722880ull
#define OFF_HB      25755648ull
#define OFF_CB      25788416ull
#define OFF_SUMF    25821184ull
#define OFF_SUMB    25853952ull
#define OFF_HD      25886720ull
#define OFF_CD      25919488ull
#define OFF_DECB    25952256ull
#define OFF_HDEC    25985024ull
#define OFF_OUTS    28082176ull
#define SCR_TOTAL   30179328ull

__device__ float g_scr[SCR_TOTAL];
__device__ __nv_bfloat16 g_Acat[(size_t)2048 * cKC];
__device__ __nv_bfloat16 g_Wcat[(size_t)cV * cKC];
__device__ __nv_bfloat16 g_WihC[3][(size_t)cG * 1536];
__device__ __nv_bfloat16 g_WhhC[3][(size_t)cG * 3072];
__device__ __nv_bfloat16 g_AE[(size_t)2048 * 1536];
__device__ __nv_bfloat16 g_AD[(size_t)2048 * 1536];
__device__ __nv_bfloat16 g_hc[3 * 32 * 3072];   // 294912 bf16 = 147456 floats

typedef unsigned long long u64;

__device__ __forceinline__ float sigf(float x) { return 1.0f / (1.0f + expf(-x)); }
__device__ __forceinline__ u64 splat2(float a) {
    u64 r; asm("mov.b64 %0, {%1, %1};" : "=l"(r) : "f"(a)); return r;
}
__device__ __forceinline__ void fma2(u64& d, u64 a, u64 b) {
    asm("fma.rn.f32x2 %0, %1, %2, %0;" : "+l"(d) : "l"(a), "l"(b));
}
__device__ __forceinline__ float2 unpk(u64 v) {
    float2 f; asm("mov.b64 {%0, %1}, %2;" : "=f"(f.x), "=f"(f.y) : "l"(v)); return f;
}
__device__ __forceinline__ unsigned smem_u32(const void* p) {
    unsigned r;
    asm("{ .reg .u64 t; cvta.to.shared.u64 t, %1; cvt.u32.u64 %0, t; }" : "=r"(r) : "l"(p));
    return r;
}
__device__ __forceinline__ void bf16split(float x, __nv_bfloat16& h, __nv_bfloat16& l) {
    h = __float2bfloat16(x);
    l = __float2bfloat16(x - __bfloat162float(h));
}

// ============ split K=1024 -> 3072 [hi|hi|lo]   (Wout, Whh_*)
__global__ void k_splitW(const float* __restrict__ W, __nv_bfloat16* __restrict__ C, int rows)
{
    int i = blockIdx.x * 256 + threadIdx.x;
    if (i >= rows * 512) return;
    int n = i >> 9, k2 = i & 511;
    float2 w = *(const float2*)&W[(size_t)n * cH + k2 * 2];
    __nv_bfloat16 h0, l0, h1, l1;
    bf16split(w.x, h0, l0); bf16split(w.y, h1, l1);
    __nv_bfloat162 hh; hh.x = h0; hh.y = h1;
    __nv_bfloat162 ll; ll.x = l0; ll.y = l1;
    __nv_bfloat162* R = (__nv_bfloat162*)(C + (size_t)n * 3072);
    R[k2] = hh; R[512 + k2] = hh; R[1024 + k2] = ll;
}

// ============ split K=1024 -> 3072 [hi|lo|hi]   (logits A)
__global__ void k_splitA(const float* __restrict__ A, __nv_bfloat16* __restrict__ C, int rows)
{
    int i = blockIdx.x * 256 + threadIdx.x;
    if (i >= rows * 512) return;
    int m = i >> 9, k2 = i & 511;
    float2 w = *(const float2*)&A[(size_t)m * cH + k2 * 2];
    __nv_bfloat16 h0, l0, h1, l1;
    bf16split(w.x, h0, l0); bf16split(w.y, h1, l1);
    __nv_bfloat162 hh; hh.x = h0; hh.y = h1;
    __nv_bfloat162 ll; ll.x = l0; ll.y = l1;
    __nv_bfloat162* R = (__nv_bfloat162*)(C + (size_t)m * 3072);
    R[k2] = hh; R[512 + k2] = ll; R[1024 + k2] = hh;
}

// ============ split K=512 -> 1536 [hi|hi|lo]   (Wih_*)
__global__ void k_splitW512(const float* __restrict__ W, __nv_bfloat16* __restrict__ C, int rows)
{
    int i = blockIdx.x * 256 + threadIdx.x;
    if (i >= rows * 256) return;
    int n = i >> 8, k2 = i & 255;
    float2 w = *(const float2*)&W[(size_t)n * cE + k2 * 2];
    __nv_bfloat16 h0, l0, h1, l1;
    bf16split(w.x, h0, l0); bf16split(w.y, h1, l1);
    __nv_bfloat162 hh; hh.x = h0; hh.y = h1;
    __nv_bfloat162 ll; ll.x = l0; ll.y = l1;
    __nv_bfloat162* R = (__nv_bfloat162*)(C + (size_t)n * 1536);
    R[k2] = hh; R[256 + k2] = hh; R[512 + k2] = ll;
}

// ============ token gather + split K=512 -> 1536 [hi|lo|hi]
__global__ void k_gather512(const int* __restrict__ tok, const float* __restrict__ emb,
                            __nv_bfloat16* __restrict__ C)
{
    int i = blockIdx.x * 256 + threadIdx.x;
    int m = i >> 8, k2 = i & 255;
    int trow = tok[(m & 31) * 64 + (m >> 5)];
    float2 w = *(const float2*)&emb[(size_t)trow * cE + k2 * 2];
    __nv_bfloat16 h0, l0, h1, l1;
    bf16split(w.x, h0, l0); bf16split(w.y, h1, l1);
    __nv_bfloat162 hh; hh.x = h0; hh.y = h1;
    __nv_bfloat162 ll; ll.x = l0; ll.y = l1;
    __nv_bfloat162* R = (__nv_bfloat162*)(C + (size_t)m * 1536);
    R[k2] = hh; R[256 + k2] = ll; R[512 + k2] = hh;
}

#define STRD 80

// ============ HMMA logits GEMM (validated)
__global__ __launch_bounds__(256, 2)
void k_logits_mma(const __nv_bfloat16* __restrict__ Acat,
                  const __nv_bfloat16* __restrict__ Wcat,
                  const float* __restrict__ bout, float* __restrict__ out)
{
    __shared__ char sm[2][2 * 128 * STRD];
    const int tid = threadIdx.x, wid = tid >> 5, lane = tid & 31;
    const int m0 = blockIdx.x * 128, n0 = blockIdx.y * 128;
    const int warp_m = (wid & 1) * 64, warp_n = (wid >> 1) * 32;

    float acc[4][4][4];
    #pragma unroll
    for (int a = 0; a < 4; a++)
        #pragma unroll
        for (int b = 0; b < 4; b++)
            #pragma unroll
            for (int d = 0; d < 4; d++) acc[a][b][d] = 0.f;

    const int g0 = tid, g1 = tid + 256;
    const int ra0 = g0 >> 2, qa0 = (g0 & 3) * 16;
    const int ra1 = g1 >> 2, qa1 = (g1 & 3) * 16;
    const char* gA0 = (const char*)(Acat + (size_t)(m0 + ra0) * cKC) + qa0;
    const char* gA1 = (const char*)(Acat + (size_t)(m0 + ra1) * cKC) + qa1;
    const char* gB0 = (const char*)(Wcat + (size_t)(n0 + ra0) * cKC) + qa0;
    const char* gB1 = (const char*)(Wcat + (size_t)(n0 + ra1) * cKC) + qa1;
    unsigned dA0 = smem_u32(sm) + ra0 * STRD + qa0;
    unsigned dA1 = smem_u32(sm) + ra1 * STRD + qa1;
    unsigned dB0 = dA0 + 128 * STRD, dB1 = dA1 + 128 * STRD;
    const unsigned bufsz = 2 * 128 * STRD;

    unsigned laA = smem_u32(sm) + (warp_m + (lane & 15)) * STRD + (lane >> 4) * 16;
    unsigned laB = smem_u32(sm) + 128 * STRD + (warp_n + (lane & 7)) * STRD + ((lane >> 3) & 1) * 16;

    asm volatile("cp.async.cg.shared.global [%0], [%1], 16;" :: "r"(dA0), "l"(gA0));
    asm volatile("cp.async.cg.shared.global [%0], [%1], 16;" :: "r"(dA1), "l"(gA1));
    asm volatile("cp.async.cg.shared.global [%0], [%1], 16;" :: "r"(dB0), "l"(gB0));
    asm volatile("cp.async.cg.shared.global [%0], [%1], 16;" :: "r"(dB1), "l"(gB1));
    asm volatile("cp.async.commit_group;");

    int buf = 0;
    for (int c = 0; c < 96; c++) {
        if (c + 1 < 96) {
            size_t go = (size_t)(c + 1) * 64;
            unsigned so = (buf ^ 1) * bufsz;
            asm volatile("cp.async.cg.shared.global [%0], [%1], 16;" :: "r"(dA0 + so), "l"(gA0 + go));
            asm volatile("cp.async.cg.shared.global [%0], [%1], 16;" :: "r"(dA1 + so), "l"(gA1 + go));
            asm volatile("cp.async.cg.shared.global [%0], [%1], 16;" :: "r"(dB0 + so), "l"(gB0 + go));
            asm volatile("cp.async.cg.shared.global [%0], [%1], 16;" :: "r"(dB1 + so), "l"(gB1 + go));
            asm volatile("cp.async.commit_group;");
            asm volatile("cp.async.wait_group 1;");
        } else {
            asm volatile("cp.async.wait_group 0;");
        }
        __syncthreads();

        unsigned so = buf * bufsz;
        #pragma unroll
        for (int ks = 0; ks < 2; ks++) {
            uint32_t af[4][4], bf[4][2];
            #pragma unroll
            for (int mf = 0; mf < 4; mf++) {
                unsigned ad = laA + so + mf * (16 * STRD) + ks * 32;
                asm volatile("ldmatrix.sync.aligned.m8n8.x4.shared.b16 {%0,%1,%2,%3}, [%4];"
                    : "=r"(af[mf][0]), "=r"(af[mf][1]), "=r"(af[mf][2]), "=r"(af[mf][3]) : "r"(ad));
            }
            #pragma unroll
            for (int nf = 0; nf < 4; nf++) {
                unsigned bd = laB + so + nf * (8 * STRD) + ks * 32;
                asm volatile("ldmatrix.sync.aligned.m8n8.x2.shared.b16 {%0,%1}, [%2];"
                    : "=r"(bf[nf][0]), "=r"(bf[nf][1]) : "r"(bd));
            }
            #pragma unroll
            for (int mf = 0; mf < 4; mf++)
                #pragma unroll
                for (int nf = 0; nf < 4; nf++) {
                    asm volatile(
                        "mma.sync.aligned.m16n8k16.row.col.f32.bf16.bf16.f32 "
                        "{%0,%1,%2,%3}, {%4,%5,%6,%7}, {%8,%9}, {%0,%1,%2,%3};"
                        : "+f"(acc[mf][nf][0]), "+f"(acc[mf][nf][1]),
                          "+f"(acc[mf][nf][2]), "+f"(acc[mf][nf][3])
                        : "r"(af[mf][0]), "r"(af[mf][1]), "r"(af[mf][2]), "r"(af[mf][3]),
                          "r"(bf[nf][0]), "r"(bf[nf][1]));
                }
        }
        __syncthreads();
        buf ^= 1;
    }

    #pragma unroll
    for (int mf = 0; mf < 4; mf++) {
        int mbase = m0 + warp_m + mf * 16 + (lane >> 2);
        int mA = mbase, mB = mbase + 8;
        size_t rbA = (size_t)((mA & 31) * 64 + (mA >> 5)) * cV;
        size_t rbB = (size_t)((mB & 31) * 64 + (mB >> 5)) * cV;
        #pragma unroll
        for (int nf = 0; nf < 4; nf++) {
            int n = n0 + warp_n + nf * 8 + (lane & 3) * 2;
            float2 bb = *(const float2*)&bout[n];
            float2 v0 = {acc[mf][nf][0] + bb.x, acc[mf][nf][1] + bb.y};
            float2 v1 = {acc[mf][nf][2] + bb.x, acc[mf][nf][3] + bb.y};
            *(float2*)&out[rbA + n] = v0;
            *(float2*)&out[rbB + n] = v1;
        }
    }
}

// ============ HMMA prep GEMM
__global__ __launch_bounds__(256, 2)
void k_prep_mma(const __nv_bfloat16* __restrict__ Acat,
                const __nv_bfloat16* __restrict__ Wcat,
                const float* __restrict__ bi, const float* __restrict__ bh,
                float* __restrict__ O)
{
    __shared__ char sm[2][2 * 128 * STRD];
    const int tid = threadIdx.x, wid = tid >> 5, lane = tid & 31;
    const int m0 = blockIdx.x * 128, n0 = blockIdx.y * 128;
    const int warp_m = (wid & 1) * 64, warp_n = (wid >> 1) * 32;

    float acc[4][4][4];
    #pragma unroll
    for (int a = 0; a < 4; a++)
        #pragma unroll
        for (int b = 0; b < 4; b++)
            #pragma unroll
            for (int d = 0; d < 4; d++) acc[a][b][d] = 0.f;

    const int g0 = tid, g1 = tid + 256;
    const int ra0 = g0 >> 2, qa0 = (g0 & 3) * 16;
    const int ra1 = g1 >> 2, qa1 = (g1 & 3) * 16;
    const char* gA0 = (const char*)(Acat + (size_t)(m0 + ra0) * 1536) + qa0;
    const char* gA1 = (const char*)(Acat + (size_t)(m0 + ra1) * 1536) + qa1;
    const char* gB0 = (const char*)(Wcat + (size_t)(n0 + ra0) * 1536) + qa0;
    const char* gB1 = (const char*)(Wcat + (size_t)(n0 + ra1) * 1536) + qa1;
    unsigned dA0 = smem_u32(sm) + ra0 * STRD + qa0;
    unsigned dA1 = smem_u32(sm) + ra1 * STRD + qa1;
    unsigned dB0 = dA0 + 128 * STRD, dB1 = dA1 + 128 * STRD;
    const unsigned bufsz = 2 * 128 * STRD;

    unsigned laA = smem_u32(sm) + (warp_m + (lane & 15)) * STRD + (lane >> 4) * 16;
    unsigned laB = smem_u32(sm) + 128 * STRD + (warp_n + (lane & 7)) * STRD + ((lane >> 3) & 1) * 16;

    asm volatile("cp.async.cg.shared.global [%0], [%1], 16;" :: "r"(dA0), "l"(gA0));
    asm volatile("cp.async.cg.shared.global [%0], [%1], 16;" :: "r"(dA1), "l"(gA1));
    asm volatile("cp.async.cg.shared.global [%0], [%1], 16;" :: "r"(dB0), "l"(gB0));
    asm volatile("cp.async.cg.shared.global [%0], [%1], 16;" :: "r"(dB1), "l"(gB1));
    asm volatile("cp.async.commit_group;");

    int buf = 0;
    for (int c = 0; c < 48; c++) {
        if (c + 1 < 48) {
            size_t go = (size_t)(c + 1) * 64;
            unsigned so = (buf ^ 1) * bufsz;
            asm volatile("cp.async.cg.shared.global [%0], [%1], 16;" :: "r"(dA0 + so), "l"(gA0 + go));
            asm volatile("cp.async.cg.shared.global [%0], [%1], 16;" :: "r"(dA1 + so), "l"(gA1 + go));
            asm volatile("cp.async.cg.shared.global [%0], [%1], 16;" :: "r"(dB0 + so), "l"(gB0 + go));
            asm volatile("cp.async.cg.shared.global [%0], [%1], 16;" :: "r"(dB1 + so), "l"(gB1 + go));
            asm volatile("cp.async.commit_group;");
            asm volatile("cp.async.wait_group 1;");
        } else {
            asm volatile("cp.async.wait_group 0;");
        }
        __syncthreads();

        unsigned so = buf * bufsz;
        #pragma unroll
        for (int ks = 0; ks < 2; ks++) {
            uint32_t af[4][4], bf[4][2];
            #pragma unroll
            for (int mf = 0; mf < 4; mf++) {
                unsigned ad = laA + so + mf * (16 * STRD) + ks * 32;
                asm volatile("ldmatrix.sync.aligned.m8n8.x4.shared.b16 {%0,%1,%2,%3}, [%4];"
                    : "=r"(af[mf][0]), "=r"(af[mf][1]), "=r"(af[mf][2]), "=r"(af[mf][3]) : "r"(ad));
            }
            #pragma unroll
            for (int nf = 0; nf < 4; nf++) {
                unsigned bd = laB + so + nf * (8 * STRD) + ks * 32;
                asm volatile("ldmatrix.sync.aligned.m8n8.x2.shared.b16 {%0,%1}, [%2];"
                    : "=r"(bf[nf][0]), "=r"(bf[nf][1]) : "r"(bd));
            }
            #pragma unroll
            for (int mf = 0; mf < 4; mf++)
                #pragma unroll
                for (int nf = 0; nf < 4; nf++) {
                    asm volatile(
                        "mma.sync.aligned.m16n8k16.row.col.f32.bf16.bf16.f32 "
                        "{%0,%1,%2,%3}, {%4,%5,%6,%7}, {%8,%9}, {%0,%1,%2,%3};"
                        : "+f"(acc[mf][nf][0]), "+f"(acc[mf][nf][1]),
                          "+f"(acc[mf][nf][2]), "+f"(acc[mf][nf][3])
                        : "r"(af[mf][0]), "r"(af[mf][1]), "r"(af[mf][2]), "r"(af[mf][3]),
                          "r"(bf[nf][0]), "r"(bf[nf][1]));
                }
        }
        __syncthreads();
        buf ^= 1;
    }

    #pragma unroll
    for (int mf = 0; mf < 4; mf++) {
        int mA = m0 + warp_m + mf * 16 + (lane >> 2);
        int mB = mA + 8;
        #pragma unroll
        for (int nf = 0; nf < 4; nf++) {
            int n = n0 + warp_n + nf * 8 + (lane & 3) * 2;
            float2 b1 = *(const float2*)&bi[n];
            float2 b2 = *(const float2*)&bh[n];
            float2 v0 = {acc[mf][nf][0] + b1.x + b2.x, acc[mf][nf][1] + b1.y + b2.y};
            float2 v1 = {acc[mf][nf][2] + b1.x + b2.x, acc[mf][nf][3] + b1.y + b2.y};
            *(float2*)&O[(size_t)mA * cG + n] = v0;
            *(float2*)&O[(size_t)mB * cG + n] = v1;
        }
    }
}

// ============ HMMA recurrent GEMM, 3-stage cp.async pipeline, ONE sync/iter
// out[b,n] = hcat[b,:3072]·WhhC[n,:3072], split-K via gridDim.z
__global__ __launch_bounds__(256, 2)
void k_step_mma(const __nv_bfloat16* __restrict__ hA0, const __nv_bfloat16* __restrict__ W0,
                float* __restrict__ out0,
                const __nv_bfloat16* __restrict__ hA1, const __nv_bfloat16* __restrict__ W1,
                float* __restrict__ out1)
{
    __shared__ char sm[3][(32 + 128) * STRD];
    const __nv_bfloat16* hA = blockIdx.y ? hA1 : hA0;
    const __nv_bfloat16* W  = blockIdx.y ? W1 : W0;
    float* out = (blockIdx.y ? out1 : out0) + (size_t)blockIdx.z * 131072;
    const int tid = threadIdx.x, wid = tid >> 5, lane = tid & 31;
    const int n0 = blockIdx.x * 128;
    const int nch = (3072 / gridDim.z) / 32;
    const size_t kbeg = (size_t)blockIdx.z * (3072 / gridDim.z) * 2;   // bytes

    float acc[2][2][4];
    #pragma unroll
    for (int a = 0; a < 2; a++)
        #pragma unroll
        for (int b = 0; b < 2; b++)
            #pragma unroll
            for (int d = 0; d < 4; d++) acc[a][b][d] = 0.f;

    const int ra = tid >> 2, qa = (tid & 3) * 16;
    const int rb0 = tid >> 2, qb = (tid & 3) * 16;
    const int rb1 = rb0 + 64;
    const char* gA  = (const char*)hA + (size_t)ra * 6144 + kbeg + qa;
    const char* gB0 = (const char*)W + (size_t)(n0 + rb0) * 6144 + kbeg + qb;
    const char* gB1 = (const char*)W + (size_t)(n0 + rb1) * 6144 + kbeg + qb;
    unsigned base = smem_u32(sm);
    unsigned dA  = base + ra * STRD + qa;
    unsigned dB0 = base + (32 + rb0) * STRD + qb;
    unsigned dB1 = base + (32 + rb1) * STRD + qb;
    const unsigned bufsz = (32 + 128) * STRD;

    unsigned laA = base + (lane & 15) * STRD + (lane >> 4) * 16;
    unsigned laB = base + 32 * STRD + (wid * 16 + (lane & 7)) * STRD + ((lane >> 3) & 1) * 16;

    // prologue: stages 0 and 1
    #pragma unroll
    for (int s = 0; s < 2; s++) {
        size_t go = (size_t)s * 64;
        unsigned so = s * bufsz;
        if (tid < 128)
            asm volatile("cp.async.cg.shared.global [%0], [%1], 16;" :: "r"(dA + so), "l"(gA + go));
        asm volatile("cp.async.cg.shared.global [%0], [%1], 16;" :: "r"(dB0 + so), "l"(gB0 + go));
        asm volatile("cp.async.cg.shared.global [%0], [%1], 16;" :: "r"(dB1 + so), "l"(gB1 + go));
        asm volatile("cp.async.commit_group;");
    }

    for (int c = 0; c < nch; c++) {
        asm volatile("cp.async.wait_group 1;");   // stage c complete
        __syncthreads();                          // data visible to all; slot (c-1)%3 free
        if (c + 2 < nch) {                        // issue stage c+2 into slot (c+2)%3
            size_t go = (size_t)(c + 2) * 64;
            unsigned so = ((c + 2) % 3) * bufsz;
            if (tid < 128)
                asm volatile("cp.async.cg.shared.global [%0], [%1], 16;" :: "r"(dA + so), "l"(gA + go));
            asm volatile("cp.async.cg.shared.global [%0], [%1], 16;" :: "r"(dB0 + so), "l"(gB0 + go));
            asm volatile("cp.async.cg.shared.global [%0], [%1], 16;" :: "r"(dB1 + so), "l"(gB1 + go));
            asm volatile("cp.async.commit_group;");
        }
        unsigned so = (c % 3) * bufsz;
        #pragma unroll
        for (int ks = 0; ks < 2; ks++) {
            uint32_t af[2][4], bf[2][2];
            #pragma unroll
            for (int mf = 0; mf < 2; mf++) {
                unsigned ad = laA + so + mf * (16 * STRD) + ks * 32;
                asm volatile("ldmatrix.sync.aligned.m8n8.x4.shared.b16 {%0,%1,%2,%3}, [%4];"
                    : "=r"(af[mf][0]), "=r"(af[mf][1]), "=r"(af[mf][2]), "=r"(af[mf][3]) : "r"(ad));
            }
            #pragma unroll
            for (int nf = 0; nf < 2; nf++) {
                unsigned bd = laB + so + nf * (8 * STRD) + ks * 32;
                asm volatile("ldmatrix.sync.aligned.m8n8.x2.shared.b16 {%0,%1}, [%2];"
                    : "=r"(bf[nf][0]), "=r"(bf[nf][1]) : "r"(bd));
            }
            #pragma unroll
            for (int mf = 0; mf < 2; mf++)
                #pragma unroll
                for (int nf = 0; nf < 2; nf++) {
                    asm volatile(
                        "mma.sync.aligned.m16n8k16.row.col.f32.bf16.bf16.f32 "
                        "{%0,%1,%2,%3}, {%4,%5,%6,%7}, {%8,%9}, {%0,%1,%2,%3};"
                        : "+f"(acc[mf][nf][0]), "+f"(acc[mf][nf][1]),
                          "+f"(acc[mf][nf][2]), "+f"(acc[mf][nf][3])
                        : "r"(af[mf][0]), "r"(af[mf][1]), "r"(af[mf][2]), "r"(af[mf][3]),
                          "r"(bf[nf][0]), "r"(bf[nf][1]));
                }
        }
    }

    #pragma unroll
    for (int mf = 0; mf < 2; mf++) {
        int rA = mf * 16 + (lane >> 2);
        int rB = rA + 8;
        #pragma unroll
        for (int nf = 0; nf < 2; nf++) {
            int n = n0 + wid * 16 + nf * 8 + (lane & 3) * 2;
            *(float2*)&out[rA * cG + n] = make_float2(acc[mf][nf][0], acc[mf][nf][1]);
            *(float2*)&out[rB * cG + n] = make_float2(acc[mf][nf][2], acc[mf][nf][3]);
        }
    }
}

// ============ encoder elementwise LSTM (+ hcat split emit)
__global__ void k_elem_enc(const float* __restrict__ gates,
                           const float* __restrict__ Gf_t, const float* __restrict__ Gb_t,
                           float* __restrict__ hf, float* __restrict__ cf,
                           float* __restrict__ hb, float* __restrict__ cb,
                           float* __restrict__ sumf, float* __restrict__ sumb,
                           __nv_bfloat16* __restrict__ hfc, __nv_bfloat16* __restrict__ hbc)
{
    int idx = blockIdx.x * 256 + threadIdx.x;
    int dir = idx >> 15;
    int u = idx & 32767;
    int b = u >> 10, j = u & 1023;
    int base = b * cG;
    const float* Gx = (dir ? Gb_t : Gf_t) + base;
    const float* p0 = gates + dir * 262144 + base;
    const float* p1 = p0 + 131072;
    float gi = Gx[j]      + p0[j]      + p1[j];
    float gf = Gx[1024+j] + p0[1024+j] + p1[1024+j];
    float gg = Gx[2048+j] + p0[2048+j] + p1[2048+j];
    float go = Gx[3072+j] + p0[3072+j] + p1[3072+j];
    float* cp = dir ? cb : cf;
    float* hp = dir ? hb : hf;
    float* sp = dir ? sumb : sumf;
    float c = sigf(gf) * cp[u] + sigf(gi) * tanhf(gg);
    cp[u] = c;
    float h = sigf(go) * tanhf(c);
    hp[u] = h;
    sp[u] += h;
    __nv_bfloat16 hh, hl; bf16split(h, hh, hl);
    __nv_bfloat16* hc = (dir ? hbc : hfc) + b * 3072;
    hc[j] = hh; hc[1024 + j] = hl; hc[2048 + j] = hh;
}

// ============ decoder elementwise LSTM (+ hcat split emit)
__global__ void k_elem_dec(const float* __restrict__ gates, const float* __restrict__ Gd_t,
                           float* __restrict__ hd, float* __restrict__ cd,
                           float* __restrict__ hdec_t, __nv_bfloat16* __restrict__ hdc)
{
    int u = blockIdx.x * 256 + threadIdx.x;
    int b = u >> 10, j = u & 1023;
    int base = b * cG;
    float gi = Gd_t[base+j], gf = Gd_t[base+1024+j];
    float gg = Gd_t[base+2048+j], go = Gd_t[base+3072+j];
    #pragma unroll
    for (int z = 0; z < 4; z++) {
        const float* p = gates + z * 131072 + base;
        gi += p[j]; gf += p[1024+j]; gg += p[2048+j]; go += p[3072+j];
    }
    float c = sigf(gf) * cd[u] + sigf(gi) * tanhf(gg);
    cd[u] = c;
    float h = sigf(go) * tanhf(c);
    hd[u] = h;
    hdec_t[u] = h;
    __nv_bfloat16 hh, hl; bf16split(h, hh, hl);
    __nv_bfloat16* hc = hdc + b * 3072;
    hc[j] = hh; hc[1024 + j] = hl; hc[2048 + j] = hh;
}

__global__ void k_zero(float* __restrict__ p, int n)
{
    int i = blockIdx.x * 256 + threadIdx.x;
    if (i < n) p[i] = 0.f;
}

__global__ void k_initdec(const float* __restrict__ hf, const float* __restrict__ hb,
                          const float* __restrict__ cf, const float* __restrict__ cb,
                          float* __restrict__ hd, float* __restrict__ cd,
                          __nv_bfloat16* __restrict__ hdc)
{
    int u = blockIdx.x * 256 + threadIdx.x;
    float h = hf[u] + hb[u];
    hd[u] = h;
    cd[u] = cf[u] + cb[u];
    int b = u >> 10, j = u & 1023;
    __nv_bfloat16 hh, hl; bf16split(h, hh, hl);
    __nv_bfloat16* hc = hdc + b * 3072;
    hc[j] = hh; hc[1024 + j] = hl; hc[2048 + j] = hh;
}

// ============ decoder constant bias partials (fp32, small)
__global__ __launch_bounds__(256) void k_decbias(
    const float* __restrict__ sumf, const float* __restrict__ sumb,
    const float* __restrict__ Wc, float* __restrict__ parts)
{
    __shared__ float As[16][33];
    __shared__ float Bs[16][128];
    const int tid = threadIdx.x, n0 = blockIdx.x * 128;
    const int kn = 2048 / gridDim.z, kbeg = blockIdx.z * kn;
    const int tx = tid & 31, ty = tid >> 5;
    float acc[4][4];
    #pragma unroll
    for (int i = 0; i < 4; i++)
        #pragma unroll
        for (int j = 0; j < 4; j++) acc[i][j] = 0.f;

    for (int k0 = kbeg; k0 < kbeg + kn; k0 += 16) {
        if (tid < 128) {
            int r = tid >> 2, c4 = (tid & 3) << 2;
            int k = k0 + c4;
            const float* src = (k < 1024) ? &sumf[r*cH + k] : &sumb[r*cH + k - 1024];
            float4 v = *(const float4*)src;
            As[c4+0][r]=v.x; As[c4+1][r]=v.y; As[c4+2][r]=v.z; As[c4+3][r]=v.w;
        }
        #pragma unroll
        for (int L = 0; L < 2; L++) {
            int flat = tid + (L << 8);
            int r = flat >> 2, c4 = (flat & 3) << 2;
            float4 v = *(const float4*)&Wc[(size_t)(n0 + r) * 3072 + 1024 + k0 + c4];
            Bs[c4+0][r]=v.x; Bs[c4+1][r]=v.y; Bs[c4+2][r]=v.z; Bs[c4+3][r]=v.w;
        }
        __syncthreads();
        #pragma unroll
        for (int kk = 0; kk < 16; kk++) {
            float a0=As[kk][ty*4+0], a1=As[kk][ty*4+1], a2=As[kk][ty*4+2], a3=As[kk][ty*4+3];
            float4 b = *(const float4*)&Bs[kk][tx*4];
            acc[0][0]+=a0*b.x; acc[0][1]+=a0*b.y; acc[0][2]+=a0*b.z; acc[0][3]+=a0*b.w;
            acc[1][0]+=a1*b.x; acc[1][1]+=a1*b.y; acc[1][2]+=a1*b.z; acc[1][3]+=a1*b.w;
            acc[2][0]+=a2*b.x; acc[2][1]+=a2*b.y; acc[2][2]+=a2*b.z; acc[2][3]+=a2*b.w;
            acc[3][0]+=a3*b.x; acc[3][1]+=a3*b.y; acc[3][2]+=a3*b.z; acc[3][3]+=a3*b.w;
        }
        __syncthreads();
    }
    float* out = parts + (size_t)blockIdx.z * 32768;
    #pragma unroll
    for (int i = 0; i < 4; i++) {
        int b = ty*4 + i;
        #pragma unroll
        for (int j = 0; j < 4; j++)
            out[b*cH + n0 + tx*4 + j] = acc[i][j];
    }
}

__global__ void k_redbias(const float* __restrict__ parts, const float* __restrict__ bc,
                          float* __restrict__ decb)
{
    int u = blockIdx.x * 256 + threadIdx.x;
    float a = bc[u & 1023];
    #pragma unroll
    for (int z = 0; z < 8; z++) a += parts[z * 32768 + u];
    decb[u] = a;
}

// ============ outs = tanh(Hdec @ Wc[:, :1024].T + decb[b])  (fp32, f32x2)
__global__ __launch_bounds__(256, 2) void k_outs(
    const float* __restrict__ A, const float* __restrict__ Wc,
    const float* __restrict__ decb, float* __restrict__ O)
{
    __shared__ float As[16][128];
    __shared__ float Bs[16][128];
    const int m0 = blockIdx.x * 128, n0 = blockIdx.y * 128;
    const int tid = threadIdx.x, tx = tid & 15, ty = tid >> 4;
    u64 acc2[8][4];
    #pragma unroll
    for (int i = 0; i < 8; i++)
        #pragma unroll
        for (int j = 0; j < 4; j++) acc2[i][j] = 0ull;

    for (int k0 = 0; k0 < cH; k0 += 16) {
        #pragma unroll
        for (int L = 0; L < 2; L++) {
            int flat = tid + (L << 8);
            int r = flat >> 2, c4 = (flat & 3) << 2;
            float4 v = *(const float4*)&A[(size_t)(m0 + r) * cH + k0 + c4];
            As[c4+0][r]=v.x; As[c4+1][r]=v.y; As[c4+2][r]=v.z; As[c4+3][r]=v.w;
        }
        #pragma unroll
        for (int L = 0; L < 2; L++) {
            int flat = tid + (L << 8);
            int r = flat >> 2, c4 = (flat & 3) << 2;
            float4 v = *(const float4*)&Wc[(size_t)(n0 + r) * 3072 + k0 + c4];
            Bs[c4+0][r]=v.x; Bs[c4+1][r]=v.y; Bs[c4+2][r]=v.z; Bs[c4+3][r]=v.w;
        }
        __syncthreads();
        #pragma unroll
        for (int kk = 0; kk < 16; kk++) {
            float4 a0 = *(const float4*)&As[kk][ty*8];
            float4 a1 = *(const float4*)&As[kk][ty*8+4];
            u64 aa[8] = {splat2(a0.x),splat2(a0.y),splat2(a0.z),splat2(a0.w),
                         splat2(a1.x),splat2(a1.y),splat2(a1.z),splat2(a1.w)};
            ulonglong2 b01 = *(const ulonglong2*)&Bs[kk][tx*8];
            ulonglong2 b23 = *(const ulonglong2*)&Bs[kk][tx*8+4];
            u64 bb[4] = {b01.x, b01.y, b23.x, b23.y};
            #pragma unroll
            for (int i = 0; i < 8; i++)
                #pragma unroll
                for (int j = 0; j < 4; j++) fma2(acc2[i][j], aa[i], bb[j]);
        }
        __syncthreads();
    }
    #pragma unroll
    for (int i = 0; i < 8; i++) {
        int m = m0 + ty*8 + i;
        #pragma unroll
        for (int j = 0; j < 4; j++) {
            int n = n0 + tx*8 + j*2;
            float2 v = unpk(acc2[i][j]);
            O[(size_t)m*cH + n]     = tanhf(v.x + decb[(m & 31) * cH + n]);
            O[(size_t)m*cH + n + 1] = tanhf(v.y + decb[(m & 31) * cH + n + 1]);
        }
    }
}

// ============ in-place log_softmax over V + argmax
__global__ void k_softmax(float* __restrict__ out, float* __restrict__ preds, int write_preds)
{
    int r = blockIdx.x;
    float* row = out + (size_t)r * cV;
    int tid = threadIdx.x;
    __shared__ float sm[256];
    __shared__ int   si[256];
    float m = -1e30f; int mi = 0;
    for (int v = tid; v < cV; v += 256) {
        float x = row[v];
        if (x > m) { m = x; mi = v; }
    }
    sm[tid] = m; si[tid] = mi;
    __syncthreads();
    for (int s = 128; s > 0; s >>= 1) {
        if (tid < s) {
            float o = sm[tid+s]; int oi = si[tid+s];
            if (o > sm[tid] || (o == sm[tid] && oi < si[tid])) { sm[tid] = o; si[tid] = oi; }
        }
        __syncthreads();
    }
    float rowmax = sm[0];
    int rowarg = si[0];
    float acc = 0.f;
    for (int v = tid; v < cV; v += 256) acc += expf(row[v] - rowmax);
    sm[tid] = acc;
    __syncthreads();
    for (int s = 128; s > 0; s >>= 1) {
        if (tid < s) sm[tid] += sm[tid+s];
        __syncthreads();
    }
    float lse = rowmax + logf(sm[0]);
    for (int v = tid; v < cV; v += 256) row[v] -= lse;
    if (tid == 0 && write_preds) preds[r] = (float)rowarg;
}

extern "C" void kernel_launch(void* const* d_in, const int* in_sizes, int n_in,
                              void* d_out, int out_size)
{
    const int*   inputs  = (const int*)d_in[0];
    const int*   targets = (const int*)d_in[1];
    const float* emb_src = (const float*)d_in[2];
    const float* Wih_f = (const float*)d_in[3];
    const float* Whh_f = (const float*)d_in[4];
    const float* bih_f = (const float*)d_in[5];
    const float* bhh_f = (const float*)d_in[6];
    const float* Wih_b = (const float*)d_in[7];
    const float* Whh_b = (const float*)d_in[8];
    const float* bih_b = (const float*)d_in[9];
    const float* bhh_b = (const float*)d_in[10];
    const float* emb_tgt = (const float*)d_in[11];
    const float* Wih_d = (const float*)d_in[12];
    const float* Whh_d = (const float*)d_in[13];
    const float* bih_d = (const float*)d_in[14];
    const float* bhh_d = (const float*)d_in[15];
    /* d_in[16] = Wattn: unused (softmax over singleton axis) */
    const float* Wc   = (const float*)d_in[17];
    const float* bc   = (const float*)d_in[18];
    const float* Wout = (const float*)d_in[19];
    const float* bout = (const float*)d_in[20];
    float* out = (float*)d_out;

    float* scr = nullptr;
    cudaGetSymbolAddress((void**)&scr, g_scr);
    __nv_bfloat16* Acat = nullptr; cudaGetSymbolAddress((void**)&Acat, g_Acat);
    __nv_bfloat16* Wcat = nullptr; cudaGetSymbolAddress((void**)&Wcat, g_Wcat);
    __nv_bfloat16* WihC = nullptr; cudaGetSymbolAddress((void**)&WihC, g_WihC);
    __nv_bfloat16* WhhC = nullptr; cudaGetSymbolAddress((void**)&WhhC, g_WhhC);
    __nv_bfloat16* AE = nullptr; cudaGetSymbolAddress((void**)&AE, g_AE);
    __nv_bfloat16* AD = nullptr; cudaGetSymbolAddress((void**)&AD, g_AD);
    __nv_bfloat16* hc = nullptr; cudaGetSymbolAddress((void**)&hc, g_hc);

    __nv_bfloat16* WihC0 = WihC;
    __nv_bfloat16* WihC1 = WihC + (size_t)cG * 1536;
    __nv_bfloat16* WihC2 = WihC + 2 * (size_t)cG * 1536;
    __nv_bfloat16* WhhC0 = WhhC;
    __nv_bfloat16* WhhC1 = WhhC + (size_t)cG * 3072;
    __nv_bfloat16* WhhC2 = WhhC + 2 * (size_t)cG * 3072;
    __nv_bfloat16* hcF = hc;
    __nv_bfloat16* hcB = hc + 98304;
    __nv_bfloat16* hcD = hc + 196608;

    float* GF    = scr + OFF_GF;
    float* GB    = scr + OFF_GB;
    float* GD    = scr + OFF_GD;
    float* GATES = scr + OFF_GATES;
    float* HF = scr + OFF_HF;  float* CF = scr + OFF_CF;
    float* HB = scr + OFF_HB;  float* CBv = scr + OFF_CB;
    float* SF = scr + OFF_SUMF; float* SB = scr + OFF_SUMB;
    float* HD = scr + OFF_HD;  float* CD = scr + OFF_CD;
    float* DECB = scr + OFF_DECB;
    float* HDEC = scr + OFF_HDEC;
    float* OUTS = scr + OFF_OUTS;

    // weight splits
    k_splitW<<<64000, 256>>>(Wout, Wcat, cV);
    k_splitW<<<8192, 256>>>(Whh_f, WhhC0, cG);
    k_splitW<<<8192, 256>>>(Whh_b, WhhC1, cG);
    k_splitW<<<8192, 256>>>(Whh_d, WhhC2, cG);
    k_splitW512<<<4096, 256>>>(Wih_f, WihC0, cG);
    k_splitW512<<<4096, 256>>>(Wih_b, WihC1, cG);
    k_splitW512<<<4096, 256>>>(Wih_d, WihC2, cG);
    k_gather512<<<2048, 256>>>(inputs, emb_src, AE);
    k_gather512<<<2048, 256>>>(targets, emb_tgt, AD);

    // batched gate pre-activations (HMMA)
    k_prep_mma<<<dim3(16, 32), 256>>>(AE, WihC0, bih_f, bhh_f, GF);
    k_prep_mma<<<dim3(16, 32), 256>>>(AE, WihC1, bih_b, bhh_b, GB);
    k_prep_mma<<<dim3(16, 32), 256>>>(AD, WihC2, bih_d, bhh_d, GD);
    k_zero<<<768, 256>>>(HF, 196608);
    // FULL hc clear: 294912 bf16 = 147456 floats (replay determinism)
    k_zero<<<576, 256>>>((float*)hc, 147456);

    // encoder
    for (int t = 0; t < cS; t++) {
        k_step_mma<<<dim3(32, 2, 2), 256>>>(hcF, WhhC0, GATES, hcB, WhhC1, GATES + 262144);
        k_elem_enc<<<256, 256>>>(GATES, GF + (size_t)t * 131072,
                                 GB + (size_t)(cS - 1 - t) * 131072,
                                 HF, CF, HB, CBv, SF, SB, hcF, hcB);
    }

    k_initdec<<<128, 256>>>(HF, HB, CF, CBv, HD, CD, hcD);
    k_decbias<<<dim3(8, 1, 8), 256>>>(SF, SB, Wc, GATES);
    k_redbias<<<128, 256>>>(GATES, bc, DECB);

    // decoder
    for (int t = 0; t < cT; t++) {
        k_step_mma<<<dim3(32, 1, 4), 256>>>(hcD, WhhC2, GATES, hcD, WhhC2, GATES);
        k_elem_dec<<<128, 256>>>(GATES, GD + (size_t)t * 131072, HD, CD,
                                 HDEC + (size_t)t * 32768, hcD);
    }

    k_outs<<<dim3(16, 8), 256>>>(HDEC, Wc, DECB, OUTS);

    // tensor-core logits
    k_splitA<<<4096, 256>>>(OUTS, Acat, 2048);
    k_logits_mma<<<dim3(16, 250), 256>>>(Acat, Wcat, bout, out);

    int write_preds = (out_size >= cB * cT * cV + cB * cT) ? 1 : 0;
    k_softmax<<<2048, 256>>>(out, out + (size_t)cB * cT * cV, write_preds);
}

// round 16
// speedup vs baseline: 1.3592x; 1.0066x over previous
#include <cuda_runtime.h>
#include <cuda_bf16.h>
#include <math.h>
#include <stdint.h>

#define cB 32
#define cS 64
#define cT 64
#define cE 512
#define cH 1024
#define cG 4096
#define cV 32000
#define cKC 3072

// ---- scratch layout (float offsets) ----
#define OFF_GF      0ull
#define OFF_GB      8388608ull
#define OFF_GD      16777216ull
#define OFF_GATES   25165824ull   // decbias parts (8 x 32768)
#define OFF_HF      25690112ull
#define OFF_CF      25722880ull
#define OFF_HB      25755648ull
#define OFF_CB      25788416ull
#define OFF_SUMF    25821184ull
#define OFF_SUMB    25853952ull
#define OFF_HD      25886720ull
#define OFF_CD      25919488ull
#define OFF_DECB    25952256ull
#define OFF_HDEC    25985024ull
#define OFF_OUTS    28082176ull
#define SCR_TOTAL   30179328ull

__device__ float g_scr[SCR_TOTAL];
__device__ float g_gates[8 * 131072];            // step split-K partials (8 slots)
__device__ __nv_bfloat16 g_Acat[(size_t)2048 * cKC];
__device__ __nv_bfloat16 g_Wcat[(size_t)cV * cKC];
__device__ __nv_bfloat16 g_WihC[3][(size_t)cG * 1536];
__device__ __nv_bfloat16 g_WhhC[3][(size_t)cG * 3072];
__device__ __nv_bfloat16 g_AE[(size_t)2048 * 1536];
__device__ __nv_bfloat16 g_AD[(size_t)2048 * 1536];
__device__ __nv_bfloat16 g_hc[3 * 32 * 3072];   // 294912 bf16 = 147456 floats

typedef unsigned long long u64;

__device__ __forceinline__ float sigf(float x) { return 1.0f / (1.0f + expf(-x)); }
__device__ __forceinline__ u64 splat2(float a) {
    u64 r; asm("mov.b64 %0, {%1, %1};" : "=l"(r) : "f"(a)); return r;
}
__device__ __forceinline__ void fma2(u64& d, u64 a, u64 b) {
    asm("fma.rn.f32x2 %0, %1, %2, %0;" : "+l"(d) : "l"(a), "l"(b));
}
__device__ __forceinline__ float2 unpk(u64 v) {
    float2 f; asm("mov.b64 {%0, %1}, %2;" : "=f"(f.x), "=f"(f.y) : "l"(v)); return f;
}
__device__ __forceinline__ unsigned smem_u32(const void* p) {
    unsigned r;
    asm("{ .reg .u64 t; cvta.to.shared.u64 t, %1; cvt.u32.u64 %0, t; }" : "=r"(r) : "l"(p));
    return r;
}
__device__ __forceinline__ void bf16split(float x, __nv_bfloat16& h, __nv_bfloat16& l) {
    h = __float2bfloat16(x);
    l = __float2bfloat16(x - __bfloat162float(h));
}

// ============ split K=1024 -> 3072 [hi|hi|lo]   (Wout, Whh_*)
__global__ void k_splitW(const float* __restrict__ W, __nv_bfloat16* __restrict__ C, int rows)
{
    int i = blockIdx.x * 256 + threadIdx.x;
    if (i >= rows * 512) return;
    int n = i >> 9, k2 = i & 511;
    float2 w = *(const float2*)&W[(size_t)n * cH + k2 * 2];
    __nv_bfloat16 h0, l0, h1, l1;
    bf16split(w.x, h0, l0); bf16split(w.y, h1, l1);
    __nv_bfloat162 hh; hh.x = h0; hh.y = h1;
    __nv_bfloat162 ll; ll.x = l0; ll.y = l1;
    __nv_bfloat162* R = (__nv_bfloat162*)(C + (size_t)n * 3072);
    R[k2] = hh; R[512 + k2] = hh; R[1024 + k2] = ll;
}

// ============ split K=1024 -> 3072 [hi|lo|hi]   (logits A)
__global__ void k_splitA(const float* __restrict__ A, __nv_bfloat16* __restrict__ C, int rows)
{
    int i = blockIdx.x * 256 + threadIdx.x;
    if (i >= rows * 512) return;
    int m = i >> 9, k2 = i & 511;
    float2 w = *(const float2*)&A[(size_t)m * cH + k2 * 2];
    __nv_bfloat16 h0, l0, h1, l1;
    bf16split(w.x, h0, l0); bf16split(w.y, h1, l1);
    __nv_bfloat162 hh; hh.x = h0; hh.y = h1;
    __nv_bfloat162 ll; ll.x = l0; ll.y = l1;
    __nv_bfloat162* R = (__nv_bfloat162*)(C + (size_t)m * 3072);
    R[k2] = hh; R[512 + k2] = ll; R[1024 + k2] = hh;
}

// ============ split K=512 -> 1536 [hi|hi|lo]   (Wih_*)
__global__ void k_splitW512(const float* __restrict__ W, __nv_bfloat16* __restrict__ C, int rows)
{
    int i = blockIdx.x * 256 + threadIdx.x;
    if (i >= rows * 256) return;
    int n = i >> 8, k2 = i & 255;
    float2 w = *(const float2*)&W[(size_t)n * cE + k2 * 2];
    __nv_bfloat16 h0, l0, h1, l1;
    bf16split(w.x, h0, l0); bf16split(w.y, h1, l1);
    __nv_bfloat162 hh; hh.x = h0; hh.y = h1;
    __nv_bfloat162 ll; ll.x = l0; ll.y = l1;
    __nv_bfloat162* R = (__nv_bfloat162*)(C + (size_t)n * 1536);
    R[k2] = hh; R[256 + k2] = hh; R[512 + k2] = ll;
}

// ============ token gather + split K=512 -> 1536 [hi|lo|hi]
__global__ void k_gather512(const int* __restrict__ tok, const float* __restrict__ emb,
                            __nv_bfloat16* __restrict__ C)
{
    int i = blockIdx.x * 256 + threadIdx.x;
    int m = i >> 8, k2 = i & 255;
    int trow = tok[(m & 31) * 64 + (m >> 5)];
    float2 w = *(const float2*)&emb[(size_t)trow * cE + k2 * 2];
    __nv_bfloat16 h0, l0, h1, l1;
    bf16split(w.x, h0, l0); bf16split(w.y, h1, l1);
    __nv_bfloat162 hh; hh.x = h0; hh.y = h1;
    __nv_bfloat162 ll; ll.x = l0; ll.y = l1;
    __nv_bfloat162* R = (__nv_bfloat162*)(C + (size_t)m * 1536);
    R[k2] = hh; R[256 + k2] = ll; R[512 + k2] = hh;
}

#define STRD 80

// ============ HMMA logits GEMM, 3-stage cp.async pipeline, one sync/iter
__global__ __launch_bounds__(256, 2)
void k_logits_mma(const __nv_bfloat16* __restrict__ Acat,
                  const __nv_bfloat16* __restrict__ Wcat,
                  const float* __restrict__ bout, float* __restrict__ out)
{
    extern __shared__ char smx[];
    const int tid = threadIdx.x, wid = tid >> 5, lane = tid & 31;
    const int m0 = blockIdx.x * 128, n0 = blockIdx.y * 128;
    const int warp_m = (wid & 1) * 64, warp_n = (wid >> 1) * 32;

    float acc[4][4][4];
    #pragma unroll
    for (int a = 0; a < 4; a++)
        #pragma unroll
        for (int b = 0; b < 4; b++)
            #pragma unroll
            for (int d = 0; d < 4; d++) acc[a][b][d] = 0.f;

    const int g0 = tid, g1 = tid + 256;
    const int ra0 = g0 >> 2, qa0 = (g0 & 3) * 16;
    const int ra1 = g1 >> 2, qa1 = (g1 & 3) * 16;
    const char* gA0 = (const char*)(Acat + (size_t)(m0 + ra0) * cKC) + qa0;
    const char* gA1 = (const char*)(Acat + (size_t)(m0 + ra1) * cKC) + qa1;
    const char* gB0 = (const char*)(Wcat + (size_t)(n0 + ra0) * cKC) + qa0;
    const char* gB1 = (const char*)(Wcat + (size_t)(n0 + ra1) * cKC) + qa1;
    unsigned base = smem_u32(smx);
    unsigned dA0 = base + ra0 * STRD + qa0;
    unsigned dA1 = base + ra1 * STRD + qa1;
    unsigned dB0 = dA0 + 128 * STRD, dB1 = dA1 + 128 * STRD;
    const unsigned bufsz = 2 * 128 * STRD;   // 20480

    unsigned laA = base + (warp_m + (lane & 15)) * STRD + (lane >> 4) * 16;
    unsigned laB = base + 128 * STRD + (warp_n + (lane & 7)) * STRD + ((lane >> 3) & 1) * 16;

    #pragma unroll
    for (int s = 0; s < 2; s++) {
        size_t go = (size_t)s * 64;
        unsigned so = s * bufsz;
        asm volatile("cp.async.cg.shared.global [%0], [%1], 16;" :: "r"(dA0 + so), "l"(gA0 + go));
        asm volatile("cp.async.cg.shared.global [%0], [%1], 16;" :: "r"(dA1 + so), "l"(gA1 + go));
        asm volatile("cp.async.cg.shared.global [%0], [%1], 16;" :: "r"(dB0 + so), "l"(gB0 + go));
        asm volatile("cp.async.cg.shared.global [%0], [%1], 16;" :: "r"(dB1 + so), "l"(gB1 + go));
        asm volatile("cp.async.commit_group;");
    }

    for (int c = 0; c < 96; c++) {
        if (c + 1 < 96) asm volatile("cp.async.wait_group 1;");
        else            asm volatile("cp.async.wait_group 0;");
        __syncthreads();
        if (c + 2 < 96) {
            size_t go = (size_t)(c + 2) * 64;
            unsigned so = ((c + 2) % 3) * bufsz;
            asm volatile("cp.async.cg.shared.global [%0], [%1], 16;" :: "r"(dA0 + so), "l"(gA0 + go));
            asm volatile("cp.async.cg.shared.global [%0], [%1], 16;" :: "r"(dA1 + so), "l"(gA1 + go));
            asm volatile("cp.async.cg.shared.global [%0], [%1], 16;" :: "r"(dB0 + so), "l"(gB0 + go));
            asm volatile("cp.async.cg.shared.global [%0], [%1], 16;" :: "r"(dB1 + so), "l"(gB1 + go));
            asm volatile("cp.async.commit_group;");
        }
        unsigned so = (c % 3) * bufsz;
        #pragma unroll
        for (int ks = 0; ks < 2; ks++) {
            uint32_t af[4][4], bf[4][2];
            #pragma unroll
            for (int mf = 0; mf < 4; mf++) {
                unsigned ad = laA + so + mf * (16 * STRD) + ks * 32;
                asm volatile("ldmatrix.sync.aligned.m8n8.x4.shared.b16 {%0,%1,%2,%3}, [%4];"
                    : "=r"(af[mf][0]), "=r"(af[mf][1]), "=r"(af[mf][2]), "=r"(af[mf][3]) : "r"(ad));
            }
            #pragma unroll
            for (int nf = 0; nf < 4; nf++) {
                unsigned bd = laB + so + nf * (8 * STRD) + ks * 32;
                asm volatile("ldmatrix.sync.aligned.m8n8.x2.shared.b16 {%0,%1}, [%2];"
                    : "=r"(bf[nf][0]), "=r"(bf[nf][1]) : "r"(bd));
            }
            #pragma unroll
            for (int mf = 0; mf < 4; mf++)
                #pragma unroll
                for (int nf = 0; nf < 4; nf++) {
                    asm volatile(
                        "mma.sync.aligned.m16n8k16.row.col.f32.bf16.bf16.f32 "
                        "{%0,%1,%2,%3}, {%4,%5,%6,%7}, {%8,%9}, {%0,%1,%2,%3};"
                        : "+f"(acc[mf][nf][0]), "+f"(acc[mf][nf][1]),
                          "+f"(acc[mf][nf][2]), "+f"(acc[mf][nf][3])
                        : "r"(af[mf][0]), "r"(af[mf][1]), "r"(af[mf][2]), "r"(af[mf][3]),
                          "r"(bf[nf][0]), "r"(bf[nf][1]));
                }
        }
    }

    #pragma unroll
    for (int mf = 0; mf < 4; mf++) {
        int mbase = m0 + warp_m + mf * 16 + (lane >> 2);
        int mA = mbase, mB = mbase + 8;
        size_t rbA = (size_t)((mA & 31) * 64 + (mA >> 5)) * cV;
        size_t rbB = (size_t)((mB & 31) * 64 + (mB >> 5)) * cV;
        #pragma unroll
        for (int nf = 0; nf < 4; nf++) {
            int n = n0 + warp_n + nf * 8 + (lane & 3) * 2;
            float2 bb = *(const float2*)&bout[n];
            float2 v0 = {acc[mf][nf][0] + bb.x, acc[mf][nf][1] + bb.y};
            float2 v1 = {acc[mf][nf][2] + bb.x, acc[mf][nf][3] + bb.y};
            *(float2*)&out[rbA + n] = v0;
            *(float2*)&out[rbB + n] = v1;
        }
    }
}

// ============ HMMA prep GEMM, 3-stage pipeline, one sync/iter
__global__ __launch_bounds__(256, 2)
void k_prep_mma(const __nv_bfloat16* __restrict__ Acat,
                const __nv_bfloat16* __restrict__ Wcat,
                const float* __restrict__ bi, const float* __restrict__ bh,
                float* __restrict__ O)
{
    extern __shared__ char smx[];
    const int tid = threadIdx.x, wid = tid >> 5, lane = tid & 31;
    const int m0 = blockIdx.x * 128, n0 = blockIdx.y * 128;
    const int warp_m = (wid & 1) * 64, warp_n = (wid >> 1) * 32;

    float acc[4][4][4];
    #pragma unroll
    for (int a = 0; a < 4; a++)
        #pragma unroll
        for (int b = 0; b < 4; b++)
            #pragma unroll
            for (int d = 0; d < 4; d++) acc[a][b][d] = 0.f;

    const int g0 = tid, g1 = tid + 256;
    const int ra0 = g0 >> 2, qa0 = (g0 & 3) * 16;
    const int ra1 = g1 >> 2, qa1 = (g1 & 3) * 16;
    const char* gA0 = (const char*)(Acat + (size_t)(m0 + ra0) * 1536) + qa0;
    const char* gA1 = (const char*)(Acat + (size_t)(m0 + ra1) * 1536) + qa1;
    const char* gB0 = (const char*)(Wcat + (size_t)(n0 + ra0) * 1536) + qa0;
    const char* gB1 = (const char*)(Wcat + (size_t)(n0 + ra1) * 1536) + qa1;
    unsigned base = smem_u32(smx);
    unsigned dA0 = base + ra0 * STRD + qa0;
    unsigned dA1 = base + ra1 * STRD + qa1;
    unsigned dB0 = dA0 + 128 * STRD, dB1 = dA1 + 128 * STRD;
    const unsigned bufsz = 2 * 128 * STRD;

    unsigned laA = base + (warp_m + (lane & 15)) * STRD + (lane >> 4) * 16;
    unsigned laB = base + 128 * STRD + (warp_n + (lane & 7)) * STRD + ((lane >> 3) & 1) * 16;

    #pragma unroll
    for (int s = 0; s < 2; s++) {
        size_t go = (size_t)s * 64;
        unsigned so = s * bufsz;
        asm volatile("cp.async.cg.shared.global [%0], [%1], 16;" :: "r"(dA0 + so), "l"(gA0 + go));
        asm volatile("cp.async.cg.shared.global [%0], [%1], 16;" :: "r"(dA1 + so), "l"(gA1 + go));
        asm volatile("cp.async.cg.shared.global [%0], [%1], 16;" :: "r"(dB0 + so), "l"(gB0 + go));
        asm volatile("cp.async.cg.shared.global [%0], [%1], 16;" :: "r"(dB1 + so), "l"(gB1 + go));
        asm volatile("cp.async.commit_group;");
    }

    for (int c = 0; c < 48; c++) {
        if (c + 1 < 48) asm volatile("cp.async.wait_group 1;");
        else            asm volatile("cp.async.wait_group 0;");
        __syncthreads();
        if (c + 2 < 48) {
            size_t go = (size_t)(c + 2) * 64;
            unsigned so = ((c + 2) % 3) * bufsz;
            asm volatile("cp.async.cg.shared.global [%0], [%1], 16;" :: "r"(dA0 + so), "l"(gA0 + go));
            asm volatile("cp.async.cg.shared.global [%0], [%1], 16;" :: "r"(dA1 + so), "l"(gA1 + go));
            asm volatile("cp.async.cg.shared.global [%0], [%1], 16;" :: "r"(dB0 + so), "l"(gB0 + go));
            asm volatile("cp.async.cg.shared.global [%0], [%1], 16;" :: "r"(dB1 + so), "l"(gB1 + go));
            asm volatile("cp.async.commit_group;");
        }
        unsigned so = (c % 3) * bufsz;
        #pragma unroll
        for (int ks = 0; ks < 2; ks++) {
            uint32_t af[4][4], bf[4][2];
            #pragma unroll
            for (int mf = 0; mf < 4; mf++) {
                unsigned ad = laA + so + mf * (16 * STRD) + ks * 32;
                asm volatile("ldmatrix.sync.aligned.m8n8.x4.shared.b16 {%0,%1,%2,%3}, [%4];"
                    : "=r"(af[mf][0]), "=r"(af[mf][1]), "=r"(af[mf][2]), "=r"(af[mf][3]) : "r"(ad));
            }
            #pragma unroll
            for (int nf = 0; nf < 4; nf++) {
                unsigned bd = laB + so + nf * (8 * STRD) + ks * 32;
                asm volatile("ldmatrix.sync.aligned.m8n8.x2.shared.b16 {%0,%1}, [%2];"
                    : "=r"(bf[nf][0]), "=r"(bf[nf][1]) : "r"(bd));
            }
            #pragma unroll
            for (int mf = 0; mf < 4; mf++)
                #pragma unroll
                for (int nf = 0; nf < 4; nf++) {
                    asm volatile(
                        "mma.sync.aligned.m16n8k16.row.col.f32.bf16.bf16.f32 "
                        "{%0,%1,%2,%3}, {%4,%5,%6,%7}, {%8,%9}, {%0,%1,%2,%3};"
                        : "+f"(acc[mf][nf][0]), "+f"(acc[mf][nf][1]),
                          "+f"(acc[mf][nf][2]), "+f"(acc[mf][nf][3])
                        : "r"(af[mf][0]), "r"(af[mf][1]), "r"(af[mf][2]), "r"(af[mf][3]),
                          "r"(bf[nf][0]), "r"(bf[nf][1]));
                }
        }
    }

    #pragma unroll
    for (int mf = 0; mf < 4; mf++) {
        int mA = m0 + warp_m + mf * 16 + (lane >> 2);
        int mB = mA + 8;
        #pragma unroll
        for (int nf = 0; nf < 4; nf++) {
            int n = n0 + warp_n + nf * 8 + (lane & 3) * 2;
            float2 b1 = *(const float2*)&bi[n];
            float2 b2 = *(const float2*)&bh[n];
            float2 v0 = {acc[mf][nf][0] + b1.x + b2.x, acc[mf][nf][1] + b1.y + b2.y};
            float2 v1 = {acc[mf][nf][2] + b1.x + b2.x, acc[mf][nf][3] + b1.y + b2.y};
            *(float2*)&O[(size_t)mA * cG + n] = v0;
            *(float2*)&O[(size_t)mB * cG + n] = v1;
        }
    }
}

// ============ HMMA recurrent GEMM, 3-stage pipeline, one sync/iter, split-K
__global__ __launch_bounds__(256, 2)
void k_step_mma(const __nv_bfloat16* __restrict__ hA0, const __nv_bfloat16* __restrict__ W0,
                float* __restrict__ out0,
                const __nv_bfloat16* __restrict__ hA1, const __nv_bfloat16* __restrict__ W1,
                float* __restrict__ out1)
{
    __shared__ char sm[3][(32 + 128) * STRD];
    const __nv_bfloat16* hA = blockIdx.y ? hA1 : hA0;
    const __nv_bfloat16* W  = blockIdx.y ? W1 : W0;
    float* out = (blockIdx.y ? out1 : out0) + (size_t)blockIdx.z * 131072;
    const int tid = threadIdx.x, wid = tid >> 5, lane = tid & 31;
    const int n0 = blockIdx.x * 128;
    const int nch = (3072 / gridDim.z) / 32;
    const size_t kbeg = (size_t)blockIdx.z * (3072 / gridDim.z) * 2;   // bytes

    float acc[2][2][4];
    #pragma unroll
    for (int a = 0; a < 2; a++)
        #pragma unroll
        for (int b = 0; b < 2; b++)
            #pragma unroll
            for (int d = 0; d < 4; d++) acc[a][b][d] = 0.f;

    const int ra = tid >> 2, qa = (tid & 3) * 16;
    const int rb0 = tid >> 2, qb = (tid & 3) * 16;
    const int rb1 = rb0 + 64;
    const char* gA  = (const char*)hA + (size_t)ra * 6144 + kbeg + qa;
    const char* gB0 = (const char*)W + (size_t)(n0 + rb0) * 6144 + kbeg + qb;
    const char* gB1 = (const char*)W + (size_t)(n0 + rb1) * 6144 + kbeg + qb;
    unsigned base = smem_u32(sm);
    unsigned dA  = base + ra * STRD + qa;
    unsigned dB0 = base + (32 + rb0) * STRD + qb;
    unsigned dB1 = base + (32 + rb1) * STRD + qb;
    const unsigned bufsz = (32 + 128) * STRD;

    unsigned laA = base + (lane & 15) * STRD + (lane >> 4) * 16;
    unsigned laB = base + 32 * STRD + (wid * 16 + (lane & 7)) * STRD + ((lane >> 3) & 1) * 16;

    #pragma unroll
    for (int s = 0; s < 2; s++) {
        size_t go = (size_t)s * 64;
        unsigned so = s * bufsz;
        if (tid < 128)
            asm volatile("cp.async.cg.shared.global [%0], [%1], 16;" :: "r"(dA + so), "l"(gA + go));
        asm volatile("cp.async.cg.shared.global [%0], [%1], 16;" :: "r"(dB0 + so), "l"(gB0 + go));
        asm volatile("cp.async.cg.shared.global [%0], [%1], 16;" :: "r"(dB1 + so), "l"(gB1 + go));
        asm volatile("cp.async.commit_group;");
    }

    for (int c = 0; c < nch; c++) {
        if (c + 1 < nch) asm volatile("cp.async.wait_group 1;");
        else             asm volatile("cp.async.wait_group 0;");
        __syncthreads();
        if (c + 2 < nch) {
            size_t go = (size_t)(c + 2) * 64;
            unsigned so = ((c + 2) % 3) * bufsz;
            if (tid < 128)
                asm volatile("cp.async.cg.shared.global [%0], [%1], 16;" :: "r"(dA + so), "l"(gA + go));
            asm volatile("cp.async.cg.shared.global [%0], [%1], 16;" :: "r"(dB0 + so), "l"(gB0 + go));
            asm volatile("cp.async.cg.shared.global [%0], [%1], 16;" :: "r"(dB1 + so), "l"(gB1 + go));
            asm volatile("cp.async.commit_group;");
        }
        unsigned so = (c % 3) * bufsz;
        #pragma unroll
        for (int ks = 0; ks < 2; ks++) {
            uint32_t af[2][4], bf[2][2];
            #pragma unroll
            for (int mf = 0; mf < 2; mf++) {
                unsigned ad = laA + so + mf * (16 * STRD) + ks * 32;
                asm volatile("ldmatrix.sync.aligned.m8n8.x4.shared.b16 {%0,%1,%2,%3}, [%4];"
                    : "=r"(af[mf][0]), "=r"(af[mf][1]), "=r"(af[mf][2]), "=r"(af[mf][3]) : "r"(ad));
            }
            #pragma unroll
            for (int nf = 0; nf < 2; nf++) {
                unsigned bd = laB + so + nf * (8 * STRD) + ks * 32;
                asm volatile("ldmatrix.sync.aligned.m8n8.x2.shared.b16 {%0,%1}, [%2];"
                    : "=r"(bf[nf][0]), "=r"(bf[nf][1]) : "r"(bd));
            }
            #pragma unroll
            for (int mf = 0; mf < 2; mf++)
                #pragma unroll
                for (int nf = 0; nf < 2; nf++) {
                    asm volatile(
                        "mma.sync.aligned.m16n8k16.row.col.f32.bf16.bf16.f32 "
                        "{%0,%1,%2,%3}, {%4,%5,%6,%7}, {%8,%9}, {%0,%1,%2,%3};"
                        : "+f"(acc[mf][nf][0]), "+f"(acc[mf][nf][1]),
                          "+f"(acc[mf][nf][2]), "+f"(acc[mf][nf][3])
                        : "r"(af[mf][0]), "r"(af[mf][1]), "r"(af[mf][2]), "r"(af[mf][3]),
                          "r"(bf[nf][0]), "r"(bf[nf][1]));
                }
        }
    }

    #pragma unroll
    for (int mf = 0; mf < 2; mf++) {
        int rA = mf * 16 + (lane >> 2);
        int rB = rA + 8;
        #pragma unroll
        for (int nf = 0; nf < 2; nf++) {
            int n = n0 + wid * 16 + nf * 8 + (lane & 3) * 2;
            *(float2*)&out[rA * cG + n] = make_float2(acc[mf][nf][0], acc[mf][nf][1]);
            *(float2*)&out[rB * cG + n] = make_float2(acc[mf][nf][2], acc[mf][nf][3]);
        }
    }
}

// ============ encoder elementwise LSTM (4 split-K partials per dir)
__global__ void k_elem_enc(const float* __restrict__ gates,
                           const float* __restrict__ Gf_t, const float* __restrict__ Gb_t,
                           float* __restrict__ hf, float* __restrict__ cf,
                           float* __restrict__ hb, float* __restrict__ cb,
                           float* __restrict__ sumf, float* __restrict__ sumb,
                           __nv_bfloat16* __restrict__ hfc, __nv_bfloat16* __restrict__ hbc)
{
    int idx = blockIdx.x * 256 + threadIdx.x;
    int dir = idx >> 15;
    int u = idx & 32767;
    int b = u >> 10, j = u & 1023;
    int base = b * cG;
    const float* Gx = (dir ? Gb_t : Gf_t) + base;
    const float* p = gates + dir * 524288 + base;
    float gi = Gx[j], gf = Gx[1024+j], gg = Gx[2048+j], go = Gx[3072+j];
    #pragma unroll
    for (int z = 0; z < 4; z++) {
        const float* pz = p + z * 131072;
        gi += pz[j]; gf += pz[1024+j]; gg += pz[2048+j]; go += pz[3072+j];
    }
    float* cp = dir ? cb : cf;
    float* hp = dir ? hb : hf;
    float* sp = dir ? sumb : sumf;
    float c = sigf(gf) * cp[u] + sigf(gi) * tanhf(gg);
    cp[u] = c;
    float h = sigf(go) * tanhf(c);
    hp[u] = h;
    sp[u] += h;
    __nv_bfloat16 hh, hl; bf16split(h, hh, hl);
    __nv_bfloat16* hc = (dir ? hbc : hfc) + b * 3072;
    hc[j] = hh; hc[1024 + j] = hl; hc[2048 + j] = hh;
}

// ============ decoder elementwise LSTM (8 split-K partials)
__global__ void k_elem_dec(const float* __restrict__ gates, const float* __restrict__ Gd_t,
                           float* __restrict__ hd, float* __restrict__ cd,
                           float* __restrict__ hdec_t, __nv_bfloat16* __restrict__ hdc)
{
    int u = blockIdx.x * 256 + threadIdx.x;
    int b = u >> 10, j = u & 1023;
    int base = b * cG;
    float gi = Gd_t[base+j], gf = Gd_t[base+1024+j];
    float gg = Gd_t[base+2048+j], go = Gd_t[base+3072+j];
    #pragma unroll
    for (int z = 0; z < 8; z++) {
        const float* p = gates + z * 131072 + base;
        gi += p[j]; gf += p[1024+j]; gg += p[2048+j]; go += p[3072+j];
    }
    float c = sigf(gf) * cd[u] + sigf(gi) * tanhf(gg);
    cd[u] = c;
    float h = sigf(go) * tanhf(c);
    hd[u] = h;
    hdec_t[u] = h;
    __nv_bfloat16 hh, hl; bf16split(h, hh, hl);
    __nv_bfloat16* hc = hdc + b * 3072;
    hc[j] = hh; hc[1024 + j] = hl; hc[2048 + j] = hh;
}

__global__ void k_zero(float* __restrict__ p, int n)
{
    int i = blockIdx.x * 256 + threadIdx.x;
    if (i < n) p[i] = 0.f;
}

__global__ void k_initdec(const float* __restrict__ hf, const float* __restrict__ hb,
                          const float* __restrict__ cf, const float* __restrict__ cb,
                          float* __restrict__ hd, float* __restrict__ cd,
                          __nv_bfloat16* __restrict__ hdc)
{
    int u = blockIdx.x * 256 + threadIdx.x;
    float h = hf[u] + hb[u];
    hd[u] = h;
    cd[u] = cf[u] + cb[u];
    int b = u >> 10, j = u & 1023;
    __nv_bfloat16 hh, hl; bf16split(h, hh, hl);
    __nv_bfloat16* hc = hdc + b * 3072;
    hc[j] = hh; hc[1024 + j] = hl; hc[2048 + j] = hh;
}

// ============ decoder constant bias partials (fp32, small)
__global__ __launch_bounds__(256) void k_decbias(
    const float* __restrict__ sumf, const float* __restrict__ sumb,
    const float* __restrict__ Wc, float* __restrict__ parts)
{
    __shared__ float As[16][33];
    __shared__ float Bs[16][128];
    const int tid = threadIdx.x, n0 = blockIdx.x * 128;
    const int kn = 2048 / gridDim.z, kbeg = blockIdx.z * kn;
    const int tx = tid & 31, ty = tid >> 5;
    float acc[4][4];
    #pragma unroll
    for (int i = 0; i < 4; i++)
        #pragma unroll
        for (int j = 0; j < 4; j++) acc[i][j] = 0.f;

    for (int k0 = kbeg; k0 < kbeg + kn; k0 += 16) {
        if (tid < 128) {
            int r = tid >> 2, c4 = (tid & 3) << 2;
            int k = k0 + c4;
            const float* src = (k < 1024) ? &sumf[r*cH + k] : &sumb[r*cH + k - 1024];
            float4 v = *(const float4*)src;
            As[c4+0][r]=v.x; As[c4+1][r]=v.y; As[c4+2][r]=v.z; As[c4+3][r]=v.w;
        }
        #pragma unroll
        for (int L = 0; L < 2; L++) {
            int flat = tid + (L << 8);
            int r = flat >> 2, c4 = (flat & 3) << 2;
            float4 v = *(const float4*)&Wc[(size_t)(n0 + r) * 3072 + 1024 + k0 + c4];
            Bs[c4+0][r]=v.x; Bs[c4+1][r]=v.y; Bs[c4+2][r]=v.z; Bs[c4+3][r]=v.w;
        }
        __syncthreads();
        #pragma unroll
        for (int kk = 0; kk < 16; kk++) {
            float a0=As[kk][ty*4+0], a1=As[kk][ty*4+1], a2=As[kk][ty*4+2], a3=As[kk][ty*4+3];
            float4 b = *(const float4*)&Bs[kk][tx*4];
            acc[0][0]+=a0*b.x; acc[0][1]+=a0*b.y; acc[0][2]+=a0*b.z; acc[0][3]+=a0*b.w;
            acc[1][0]+=a1*b.x; acc[1][1]+=a1*b.y; acc[1][2]+=a1*b.z; acc[1][3]+=a1*b.w;
            acc[2][0]+=a2*b.x; acc[2][1]+=a2*b.y; acc[2][2]+=a2*b.z; acc[2][3]+=a2*b.w;
            acc[3][0]+=a3*b.x; acc[3][1]+=a3*b.y; acc[3][2]+=a3*b.z; acc[3][3]+=a3*b.w;
        }
        __syncthreads();
    }
    float* out = parts + (size_t)blockIdx.z * 32768;
    #pragma unroll
    for (int i = 0; i < 4; i++) {
        int b = ty*4 + i;
        #pragma unroll
        for (int j = 0; j < 4; j++)
            out[b*cH + n0 + tx*4 + j] = acc[i][j];
    }
}

__global__ void k_redbias(const float* __restrict__ parts, const float* __restrict__ bc,
                          float* __restrict__ decb)
{
    int u = blockIdx.x * 256 + threadIdx.x;
    float a = bc[u & 1023];
    #pragma unroll
    for (int z = 0; z < 8; z++) a += parts[z * 32768 + u];
    decb[u] = a;
}

// ============ outs = tanh(Hdec @ Wc[:, :1024].T + decb[b])  (fp32, f32x2)
__global__ __launch_bounds__(256, 2) void k_outs(
    const float* __restrict__ A, const float* __restrict__ Wc,
    const float* __restrict__ decb, float* __restrict__ O)
{
    __shared__ float As[16][128];
    __shared__ float Bs[16][128];
    const int m0 = blockIdx.x * 128, n0 = blockIdx.y * 128;
    const int tid = threadIdx.x, tx = tid & 15, ty = tid >> 4;
    u64 acc2[8][4];
    #pragma unroll
    for (int i = 0; i < 8; i++)
        #pragma unroll
        for (int j = 0; j < 4; j++) acc2[i][j] = 0ull;

    for (int k0 = 0; k0 < cH; k0 += 16) {
        #pragma unroll
        for (int L = 0; L < 2; L++) {
            int flat = tid + (L << 8);
            int r = flat >> 2, c4 = (flat & 3) << 2;
            float4 v = *(const float4*)&A[(size_t)(m0 + r) * cH + k0 + c4];
            As[c4+0][r]=v.x; As[c4+1][r]=v.y; As[c4+2][r]=v.z; As[c4+3][r]=v.w;
        }
        #pragma unroll
        for (int L = 0; L < 2; L++) {
            int flat = tid + (L << 8);
            int r = flat >> 2, c4 = (flat & 3) << 2;
            float4 v = *(const float4*)&Wc[(size_t)(n0 + r) * 3072 + k0 + c4];
            Bs[c4+0][r]=v.x; Bs[c4+1][r]=v.y; Bs[c4+2][r]=v.z; Bs[c4+3][r]=v.w;
        }
        __syncthreads();
        #pragma unroll
        for (int kk = 0; kk < 16; kk++) {
            float4 a0 = *(const float4*)&As[kk][ty*8];
            float4 a1 = *(const float4*)&As[kk][ty*8+4];
            u64 aa[8] = {splat2(a0.x),splat2(a0.y),splat2(a0.z),splat2(a0.w),
                         splat2(a1.x),splat2(a1.y),splat2(a1.z),splat2(a1.w)};
            ulonglong2 b01 = *(const ulonglong2*)&Bs[kk][tx*8];
            ulonglong2 b23 = *(const ulonglong2*)&Bs[kk][tx*8+4];
            u64 bb[4] = {b01.x, b01.y, b23.x, b23.y};
            #pragma unroll
            for (int i = 0; i < 8; i++)
                #pragma unroll
                for (int j = 0; j < 4; j++) fma2(acc2[i][j], aa[i], bb[j]);
        }
        __syncthreads();
    }
    #pragma unroll
    for (int i = 0; i < 8; i++) {
        int m = m0 + ty*8 + i;
        #pragma unroll
        for (int j = 0; j < 4; j++) {
            int n = n0 + tx*8 + j*2;
            float2 v = unpk(acc2[i][j]);
            O[(size_t)m*cH + n]     = tanhf(v.x + decb[(m & 31) * cH + n]);
            O[(size_t)m*cH + n + 1] = tanhf(v.y + decb[(m & 31) * cH + n + 1]);
        }
    }
}

// ============ in-place log_softmax over V + argmax
__global__ void k_softmax(float* __restrict__ out, float* __restrict__ preds, int write_preds)
{
    int r = blockIdx.x;
    float* row = out + (size_t)r * cV;
    int tid = threadIdx.x;
    __shared__ float sm[256];
    __shared__ int   si[256];
    float m = -1e30f; int mi = 0;
    for (int v = tid; v < cV; v += 256) {
        float x = row[v];
        if (x > m) { m = x; mi = v; }
    }
    sm[tid] = m; si[tid] = mi;
    __syncthreads();
    for (int s = 128; s > 0; s >>= 1) {
        if (tid < s) {
            float o = sm[tid+s]; int oi = si[tid+s];
            if (o > sm[tid] || (o == sm[tid] && oi < si[tid])) { sm[tid] = o; si[tid] = oi; }
        }
        __syncthreads();
    }
    float rowmax = sm[0];
    int rowarg = si[0];
    float acc = 0.f;
    for (int v = tid; v < cV; v += 256) acc += expf(row[v] - rowmax);
    sm[tid] = acc;
    __syncthreads();
    for (int s = 128; s > 0; s >>= 1) {
        if (tid < s) sm[tid] += sm[tid+s];
        __syncthreads();
    }
    float lse = rowmax + logf(sm[0]);
    for (int v = tid; v < cV; v += 256) row[v] -= lse;
    if (tid == 0 && write_preds) preds[r] = (float)rowarg;
}

extern "C" void kernel_launch(void* const* d_in, const int* in_sizes, int n_in,
                              void* d_out, int out_size)
{
    const int*   inputs  = (const int*)d_in[0];
    const int*   targets = (const int*)d_in[1];
    const float* emb_src = (const float*)d_in[2];
    const float* Wih_f = (const float*)d_in[3];
    const float* Whh_f = (const float*)d_in[4];
    const float* bih_f = (const float*)d_in[5];
    const float* bhh_f = (const float*)d_in[6];
    const float* Wih_b = (const float*)d_in[7];
    const float* Whh_b = (const float*)d_in[8];
    const float* bih_b = (const float*)d_in[9];
    const float* bhh_b = (const float*)d_in[10];
    const float* emb_tgt = (const float*)d_in[11];
    const float* Wih_d = (const float*)d_in[12];
    const float* Whh_d = (const float*)d_in[13];
    const float* bih_d = (const float*)d_in[14];
    const float* bhh_d = (const float*)d_in[15];
    /* d_in[16] = Wattn: unused (softmax over singleton axis) */
    const float* Wc   = (const float*)d_in[17];
    const float* bc   = (const float*)d_in[18];
    const float* Wout = (const float*)d_in[19];
    const float* bout = (const float*)d_in[20];
    float* out = (float*)d_out;

    float* scr = nullptr;
    cudaGetSymbolAddress((void**)&scr, g_scr);
    float* GT = nullptr;
    cudaGetSymbolAddress((void**)&GT, g_gates);
    __nv_bfloat16* Acat = nullptr; cudaGetSymbolAddress((void**)&Acat, g_Acat);
    __nv_bfloat16* Wcat = nullptr; cudaGetSymbolAddress((void**)&Wcat, g_Wcat);
    __nv_bfloat16* WihC = nullptr; cudaGetSymbolAddress((void**)&WihC, g_WihC);
    __nv_bfloat16* WhhC = nullptr; cudaGetSymbolAddress((void**)&WhhC, g_WhhC);
    __nv_bfloat16* AE = nullptr; cudaGetSymbolAddress((void**)&AE, g_AE);
    __nv_bfloat16* AD = nullptr; cudaGetSymbolAddress((void**)&AD, g_AD);
    __nv_bfloat16* hc = nullptr; cudaGetSymbolAddress((void**)&hc, g_hc);

    __nv_bfloat16* WihC0 = WihC;
    __nv_bfloat16* WihC1 = WihC + (size_t)cG * 1536;
    __nv_bfloat16* WihC2 = WihC + 2 * (size_t)cG * 1536;
    __nv_bfloat16* WhhC0 = WhhC;
    __nv_bfloat16* WhhC1 = WhhC + (size_t)cG * 3072;
    __nv_bfloat16* WhhC2 = WhhC + 2 * (size_t)cG * 3072;
    __nv_bfloat16* hcF = hc;
    __nv_bfloat16* hcB = hc + 98304;
    __nv_bfloat16* hcD = hc + 196608;

    float* GF    = scr + OFF_GF;
    float* GB    = scr + OFF_GB;
    float* GD    = scr + OFF_GD;
    float* GATES = scr + OFF_GATES;
    float* HF = scr + OFF_HF;  float* CF = scr + OFF_CF;
    float* HB = scr + OFF_HB;  float* CBv = scr + OFF_CB;
    float* SF = scr + OFF_SUMF; float* SB = scr + OFF_SUMB;
    float* HD = scr + OFF_HD;  float* CD = scr + OFF_CD;
    float* DECB = scr + OFF_DECB;
    float* HDEC = scr + OFF_HDEC;
    float* OUTS = scr + OFF_OUTS;

    cudaFuncSetAttribute(k_logits_mma, cudaFuncAttributeMaxDynamicSharedMemorySize, 61440);
    cudaFuncSetAttribute(k_prep_mma, cudaFuncAttributeMaxDynamicSharedMemorySize, 61440);

    // weight splits
    k_splitW<<<64000, 256>>>(Wout, Wcat, cV);
    k_splitW<<<8192, 256>>>(Whh_f, WhhC0, cG);
    k_splitW<<<8192, 256>>>(Whh_b, WhhC1, cG);
    k_splitW<<<8192, 256>>>(Whh_d, WhhC2, cG);
    k_splitW512<<<4096, 256>>>(Wih_f, WihC0, cG);
    k_splitW512<<<4096, 256>>>(Wih_b, WihC1, cG);
    k_splitW512<<<4096, 256>>>(Wih_d, WihC2, cG);
    k_gather512<<<2048, 256>>>(inputs, emb_src, AE);
    k_gather512<<<2048, 256>>>(targets, emb_tgt, AD);

    // batched gate pre-activations (HMMA, 3-stage pipeline)
    k_prep_mma<<<dim3(16, 32), 256, 61440>>>(AE, WihC0, bih_f, bhh_f, GF);
    k_prep_mma<<<dim3(16, 32), 256, 61440>>>(AE, WihC1, bih_b, bhh_b, GB);
    k_prep_mma<<<dim3(16, 32), 256, 61440>>>(AD, WihC2, bih_d, bhh_d, GD);
    k_zero<<<768, 256>>>(HF, 196608);
    // FULL hc clear: 294912 bf16 = 147456 floats (replay determinism)
    k_zero<<<576, 256>>>((float*)hc, 147456);

    // encoder (split-K 4 per dir -> 24 serial iters per step)
    for (int t = 0; t < cS; t++) {
        k_step_mma<<<dim3(32, 2, 4), 256>>>(hcF, WhhC0, GT, hcB, WhhC1, GT + 524288);
        k_elem_enc<<<256, 256>>>(GT, GF + (size_t)t * 131072,
                                 GB + (size_t)(cS - 1 - t) * 131072,
                                 HF, CF, HB, CBv, SF, SB, hcF, hcB);
    }

    k_initdec<<<128, 256>>>(HF, HB, CF, CBv, HD, CD, hcD);
    k_decbias<<<dim3(8, 1, 8), 256>>>(SF, SB, Wc, GATES);
    k_redbias<<<128, 256>>>(GATES, bc, DECB);

    // decoder (split-K 8 -> 12 serial iters per step)
    for (int t = 0; t < cT; t++) {
        k_step_mma<<<dim3(32, 1, 8), 256>>>(hcD, WhhC2, GT, hcD, WhhC2, GT);
        k_elem_dec<<<128, 256>>>(GT, GD + (size_t)t * 131072, HD, CD,
                                 HDEC + (size_t)t * 32768, hcD);
    }

    k_outs<<<dim3(16, 8), 256>>>(HDEC, Wc, DECB, OUTS);

    // tensor-core logits (3-stage pipeline)
    k_splitA<<<4096, 256>>>(OUTS, Acat, 2048);
    k_logits_mma<<<dim3(16, 250), 256, 61440>>>(Acat, Wcat, bout, out);

    int write_preds = (out_size >= cB * cT * cV + cB * cT) ? 1 : 0;
    k_softmax<<<2048, 256>>>(out, out + (size_t)cB * cT * cV, write_preds);
}